// round 11
// baseline (speedup 1.0000x reference)
#include <cuda_runtime.h>
#include <cuda_bf16.h>
#include <math.h>
#include <stdint.h>

#define N_NODES 50000
#define N_EDGES 800000
#define C1 512
#define C2 256
#define C3 128
#define NGRAPH 100
#define NBLK ((N_NODES + 127) / 128)   // 391
#define NPAD (NBLK * 128)              // 50048

#define SCAN_TILE 256
#define SCAN_BLOCKS ((N_NODES + SCAN_TILE - 1) / SCAN_TILE)  // 196

// ------------------------- helpers -------------------------
__device__ __forceinline__ uint32_t smem_u32(const void* p) {
    uint32_t a;
    asm("{ .reg .u64 t; cvta.to.shared.u64 t, %1; cvt.u32.u64 %0, t; }" : "=r"(a) : "l"(p));
    return a;
}
__device__ __forceinline__ uint32_t sw128(uint32_t o) { return o ^ ((o >> 3) & 0x70); }

__device__ __forceinline__ uint32_t split2(float v0, float v1, uint32_t& lo_out) {
    __nv_bfloat16 h0 = __float2bfloat16(v0);
    __nv_bfloat16 h1 = __float2bfloat16(v1);
    __nv_bfloat16 l0 = __float2bfloat16(v0 - __bfloat162float(h0));
    __nv_bfloat16 l1 = __float2bfloat16(v1 - __bfloat162float(h1));
    __nv_bfloat162 hp = __halves2bfloat162(h0, h1);
    __nv_bfloat162 lp = __halves2bfloat162(l0, l1);
    lo_out = *reinterpret_cast<uint32_t*>(&lp);
    return *reinterpret_cast<uint32_t*>(&hp);
}

__device__ __forceinline__ void ldsm4(uint32_t* r, uint32_t addr) {
    asm volatile("ldmatrix.sync.aligned.m8n8.x4.shared.b16 {%0,%1,%2,%3}, [%4];"
                 : "=r"(r[0]), "=r"(r[1]), "=r"(r[2]), "=r"(r[3]) : "r"(addr));
}

__device__ __forceinline__ void mma_bf16(float* c, const uint32_t* a, const uint32_t* b) {
    asm volatile(
        "mma.sync.aligned.m16n8k16.row.col.f32.bf16.bf16.f32 "
        "{%0,%1,%2,%3}, {%4,%5,%6,%7}, {%8,%9}, {%0,%1,%2,%3};"
        : "+f"(c[0]), "+f"(c[1]), "+f"(c[2]), "+f"(c[3])
        : "r"(a[0]), "r"(a[1]), "r"(a[2]), "r"(a[3]), "r"(b[0]), "r"(b[1]));
}

// ------------------------- scratch (device globals) -------------------------
__device__ int   g_cnt[N_NODES];
__device__ int   g_cur[N_NODES];
__device__ int   g_off[N_NODES + 1];
__device__ unsigned int g_state[SCAN_BLOCKS];
__device__ unsigned int g_done;
__device__ float g_dis[N_NODES];
__device__ int   g_row[N_EDGES];
__device__ float g_nrm[N_EDGES];

__device__ __align__(16) float g_aggx[N_NODES * 3];
__device__ __align__(16) float g_m2[(size_t)N_NODES * C2];
__device__ __align__(16) float g_m3[(size_t)N_NODES * C3];
__device__ __align__(16) float g_pool[NGRAPH * C3];
__device__ float g_winv[NGRAPH];

// bf16 split weights (transposed to [N][K]) and h2 splits
__device__ __align__(16) __nv_bfloat16 g_Wt2h[C2 * C1];
__device__ __align__(16) __nv_bfloat16 g_Wt2l[C2 * C1];
__device__ __align__(16) __nv_bfloat16 g_Wt3h[C3 * C2];
__device__ __align__(16) __nv_bfloat16 g_Wt3l[C3 * C2];
__device__ __align__(16) __nv_bfloat16 g_h2h[(size_t)NPAD * C2];  // pad rows stay zero
__device__ __align__(16) __nv_bfloat16 g_h2l[(size_t)NPAD * C2];

// ------------------------- zero counts + scan state -------------------------
__global__ void k_zero() {
    int i = blockIdx.x * blockDim.x + threadIdx.x;
    if (i < N_NODES) g_cnt[i] = 0;
    if (i < SCAN_BLOCKS) g_state[i] = 0u;
}

__global__ void k_count(const int* __restrict__ ei) {
    int e = blockIdx.x * blockDim.x + threadIdx.x;
    if (e < N_EDGES) atomicAdd(&g_cnt[ei[N_EDGES + e]], 1);
}

// single-pass scan with decoupled lookback (+ dis + g_cur zero + aggx self-loop init)
__global__ void k_scan(const float* __restrict__ x) {
    __shared__ int sm[SCAN_TILE];
    __shared__ int sprefix;
    int tid = threadIdx.x;
    int b = blockIdx.x;
    int i = b * SCAN_TILE + tid;
    int v = 0;
    if (i < N_NODES) {
        v = g_cnt[i];
        float dd = 1.0f / (float)(v + 1);
        g_dis[i] = rsqrtf((float)(v + 1));  // +1 self-loop
        g_cur[i] = 0;
        // self-loop contribution (overwrites -> replay-safe reset)
        g_aggx[i * 3 + 0] = dd * x[i * 3 + 0];
        g_aggx[i * 3 + 1] = dd * x[i * 3 + 1];
        g_aggx[i * 3 + 2] = dd * x[i * 3 + 2];
    }
    sm[tid] = v;
    __syncthreads();
#pragma unroll
    for (int ofs = 1; ofs < SCAN_TILE; ofs <<= 1) {
        int t = (tid >= ofs) ? sm[tid - ofs] : 0;
        __syncthreads();
        sm[tid] += t;
        __syncthreads();
    }
    if (tid == 0) {
        unsigned int total = (unsigned int)sm[SCAN_TILE - 1];
        atomicExch(&g_state[b], (1u << 30) | total);
        unsigned int ex = 0;
        for (int j = b - 1; j >= 0; j--) {
            unsigned int s;
            do { s = atomicAdd(&g_state[j], 0u); } while (s == 0u);
            ex += s & 0x3FFFFFFFu;
            if (s & (1u << 31)) break;
        }
        atomicExch(&g_state[b], (1u << 31) | (ex + total));
        sprefix = (int)ex;
    }
    __syncthreads();
    if (i < N_NODES) g_off[i + 1] = sprefix + sm[tid];
    if (b == 0 && tid == 0) g_off[0] = 0;
}

// fill CSR + edge-parallel aggx accumulation (fused — kills k_aggx)
__global__ void k_fill(const int* __restrict__ ei, const float* __restrict__ x) {
    int e = blockIdx.x * blockDim.x + threadIdx.x;
    if (e < N_EDGES) {
        int row = ei[e];
        int col = ei[N_EDGES + e];
        float w = g_dis[row] * g_dis[col];
        int pos = g_off[col] + atomicAdd(&g_cur[col], 1);
        g_row[pos] = row;
        g_nrm[pos] = w;
        float x0 = x[row * 3 + 0], x1 = x[row * 3 + 1], x2 = x[row * 3 + 2];
        atomicAdd(&g_aggx[col * 3 + 0], w * x0);
        atomicAdd(&g_aggx[col * 3 + 1], w * x1);
        atomicAdd(&g_aggx[col * 3 + 2], w * x2);
    }
}

// ------------------------- side-stream prep: weight split + graph counts + pool zero -----
__global__ void k_prep(const float* __restrict__ W2, const float* __restrict__ W3,
                       const int* __restrict__ batch) {
    int idx = blockIdx.x * 256 + threadIdx.x;
    if (idx < C1 * C2) {
        int n = idx / C1, k = idx % C1;
        float v = W2[(size_t)k * C2 + n];
        __nv_bfloat16 h = __float2bfloat16(v);
        g_Wt2h[idx] = h;
        g_Wt2l[idx] = __float2bfloat16(v - __bfloat162float(h));
    }
    int idx3 = idx - C1 * C2;
    if (idx3 >= 0 && idx3 < C2 * C3) {
        int n = idx3 / C2, k = idx3 % C2;
        float v = W3[(size_t)k * C3 + n];
        __nv_bfloat16 h = __float2bfloat16(v);
        g_Wt3h[idx3] = h;
        g_Wt3l[idx3] = __float2bfloat16(v - __bfloat162float(h));
    }
    if (idx < NGRAPH * C3) g_pool[idx] = 0.0f;
    if (idx < NGRAPH) {
        int lo = 0, hi = N_NODES;
        while (lo < hi) { int m = (lo + hi) >> 1; if (batch[m] < idx) lo = m + 1; else hi = m; }
        int s = lo;
        lo = 0; hi = N_NODES;
        while (lo < hi) { int m = (lo + hi) >> 1; if (batch[m] < idx + 1) lo = m + 1; else hi = m; }
        int cnt = lo - s;
        g_winv[idx] = 1.0f / (float)(cnt > 0 ? cnt : 1);
    }
}

// ===================== HMMA split-bf16 GEMM (single-buffered — R7 form) =====================
// Inter-CTA overlap (2 CTAs/SM) hides the fill phase; intra-CTA double-buffering
// measured WORSE (R8: +20us) — do not reintroduce.

#define G2_B1  0
#define G2_W1  2048
#define G2_AX  8192
#define G2_AHI 10240
#define G2_ALO 26624
#define G2_BHI 43008
#define G2_BLO 51200
#define SMEM_G2 59392
#define G3_AHI 0
#define G3_ALO 16384
#define G3_BHI 32768
#define G3_BLO 40960
#define SMEM_G3 49152

template <int K, int NTOT, bool GENA>
__global__ __launch_bounds__(256) void k_gemm_mma(
    const float* __restrict__ aggx, const float* __restrict__ W1,
    const float* __restrict__ b1,
    const __nv_bfloat16* __restrict__ Agh, const __nv_bfloat16* __restrict__ Agl,
    const __nv_bfloat16* __restrict__ Bgh, const __nv_bfloat16* __restrict__ Bgl,
    float* __restrict__ Cout) {
    extern __shared__ char smem[];
    const uint32_t sb = smem_u32(smem);
    const int tid = threadIdx.x;
    const int lane = tid & 31;
    const int wid = tid >> 5;
    const int wm = wid >> 1;
    const int wn = wid & 1;
    const int rowBase = blockIdx.y * 128;
    const int colBase = blockIdx.x * 64;

    constexpr int OAH = GENA ? G2_AHI : G3_AHI;
    constexpr int OAL = GENA ? G2_ALO : G3_ALO;
    constexpr int OBH = GENA ? G2_BHI : G3_BHI;
    constexpr int OBL = GENA ? G2_BLO : G3_BLO;

    float* b1s = (float*)(smem + G2_B1);
    float* W1s = (float*)(smem + G2_W1);
    float(*ax)[4] = (float(*)[4])(smem + G2_AX);

    if constexpr (GENA) {
        for (int i = tid; i < C1; i += 256) b1s[i] = b1[i];
        for (int i = tid; i < 3 * C1; i += 256) W1s[i] = W1[i];
        for (int i = tid; i < 128 * 3; i += 256) {
            int r = i / 3, j = i % 3;
            int gr = rowBase + r;
            ax[r][j] = (gr < N_NODES) ? aggx[gr * 3 + j] : 0.0f;
        }
        __syncthreads();
    }

    float acc[2][4][4];
#pragma unroll
    for (int mt = 0; mt < 2; mt++)
#pragma unroll
        for (int nt = 0; nt < 4; nt++)
#pragma unroll
            for (int j = 0; j < 4; j++) acc[mt][nt][j] = 0.0f;

    const int quad = lane >> 3;
    const int lr = lane & 7;

    for (int k0 = 0; k0 < K; k0 += 64) {
        if constexpr (GENA) {
            const int kp = tid & 31;
            const int rg = tid >> 5;
            const int k = k0 + kp * 2;
            const float w0a = W1s[k], w0b = W1s[k + 1];
            const float w1a = W1s[C1 + k], w1b = W1s[C1 + k + 1];
            const float w2a = W1s[2 * C1 + k], w2b = W1s[2 * C1 + k + 1];
            const float ba = b1s[k], bb = b1s[k + 1];
#pragma unroll 4
            for (int rr = 0; rr < 16; rr++) {
                int r = rg * 16 + rr;
                float a0 = ax[r][0], a1 = ax[r][1], a2 = ax[r][2];
                float v0 = fmaxf(ba + a0 * w0a + a1 * w1a + a2 * w2a, 0.0f);
                float v1 = fmaxf(bb + a0 * w0b + a1 * w1b + a2 * w2b, 0.0f);
                if (rowBase + r >= N_NODES) { v0 = 0.0f; v1 = 0.0f; }
                uint32_t lw, hw = split2(v0, v1, lw);
                uint32_t so = sw128((uint32_t)(r * 128 + kp * 4));
                *(uint32_t*)(smem + OAH + so) = hw;
                *(uint32_t*)(smem + OAL + so) = lw;
            }
        } else {
#pragma unroll
            for (int i = 0; i < 4; i++) {
                int idx = tid + 256 * i;
                int r = idx >> 3, ch = idx & 7;
                size_t src = (size_t)(rowBase + r) * K + k0 + ch * 8;
                uint4 vh = *(const uint4*)(Agh + src);
                uint4 vl = *(const uint4*)(Agl + src);
                uint32_t so = sw128((uint32_t)(r * 128 + ch * 16));
                *(uint4*)(smem + OAH + so) = vh;
                *(uint4*)(smem + OAL + so) = vl;
            }
        }
#pragma unroll
        for (int i = 0; i < 2; i++) {
            int idx = tid + 256 * i;
            int n = idx >> 3, ch = idx & 7;
            size_t src = (size_t)(colBase + n) * K + k0 + ch * 8;
            uint4 vh = *(const uint4*)(Bgh + src);
            uint4 vl = *(const uint4*)(Bgl + src);
            uint32_t so = sw128((uint32_t)(n * 128 + ch * 16));
            *(uint4*)(smem + OBH + so) = vh;
            *(uint4*)(smem + OBL + so) = vl;
        }
        __syncthreads();

#pragma unroll
        for (int ks = 0; ks < 4; ks++) {
            uint32_t ahi[2][4], alo[2][4];
#pragma unroll
            for (int mt = 0; mt < 2; mt++) {
                int row = wm * 32 + mt * 16 + (quad & 1) * 8 + lr;
                uint32_t kb = ks * 32 + (quad >> 1) * 16;
                uint32_t so = sw128((uint32_t)(row * 128) + kb);
                ldsm4(ahi[mt], sb + OAH + so);
                ldsm4(alo[mt], sb + OAL + so);
            }
            uint32_t bhi[4][2], blo[4][2];
#pragma unroll
            for (int p = 0; p < 2; p++) {
                int n = wn * 32 + p * 16 + (quad >> 1) * 8 + lr;
                uint32_t kb = ks * 32 + (quad & 1) * 16;
                uint32_t so = sw128((uint32_t)(n * 128) + kb);
                uint32_t rh[4], rl[4];
                ldsm4(rh, sb + OBH + so);
                ldsm4(rl, sb + OBL + so);
                bhi[p * 2][0] = rh[0]; bhi[p * 2][1] = rh[1];
                bhi[p * 2 + 1][0] = rh[2]; bhi[p * 2 + 1][1] = rh[3];
                blo[p * 2][0] = rl[0]; blo[p * 2][1] = rl[1];
                blo[p * 2 + 1][0] = rl[2]; blo[p * 2 + 1][1] = rl[3];
            }
#pragma unroll
            for (int mt = 0; mt < 2; mt++)
#pragma unroll
                for (int nt = 0; nt < 4; nt++) {
                    mma_bf16(acc[mt][nt], ahi[mt], bhi[nt]);
                    mma_bf16(acc[mt][nt], ahi[mt], blo[nt]);
                    mma_bf16(acc[mt][nt], alo[mt], bhi[nt]);
                }
        }
        __syncthreads();
    }

#pragma unroll
    for (int mt = 0; mt < 2; mt++) {
        int r0 = rowBase + wm * 32 + mt * 16 + (lane >> 2);
        int r1 = r0 + 8;
#pragma unroll
        for (int nt = 0; nt < 4; nt++) {
            int c = colBase + wn * 32 + nt * 8 + (lane & 3) * 2;
            if (r0 < N_NODES)
                *(float2*)(Cout + (size_t)r0 * NTOT + c) = make_float2(acc[mt][nt][0], acc[mt][nt][1]);
            if (r1 < N_NODES)
                *(float2*)(Cout + (size_t)r1 * NTOT + c) = make_float2(acc[mt][nt][2], acc[mt][nt][3]);
        }
    }
}

// ------------------------- CSR aggregation -------------------------
// agg2: h2 = relu(Anorm @ m2 + b2), output split to bf16 hi/lo
__global__ void k_agg2(const float* __restrict__ m, const float* __restrict__ bias) {
    int i = blockIdx.x * 4 + threadIdx.y;
    if (i >= N_NODES) return;
    int c4 = threadIdx.x;  // 0..63
    const float4* m4 = (const float4*)m;
    float d = g_dis[i];
    float dd = d * d;
    float4 v = m4[(size_t)i * (C2 / 4) + c4];
    float4 acc = make_float4(dd * v.x, dd * v.y, dd * v.z, dd * v.w);
    int e0 = g_off[i], e1 = g_off[i + 1];
    for (int e = e0; e < e1; e++) {
        int r = g_row[e];
        float w = g_nrm[e];
        float4 u = m4[(size_t)r * (C2 / 4) + c4];
        acc.x = fmaf(w, u.x, acc.x);
        acc.y = fmaf(w, u.y, acc.y);
        acc.z = fmaf(w, u.z, acc.z);
        acc.w = fmaf(w, u.w, acc.w);
    }
    float4 b = ((const float4*)bias)[c4];
    float ox = fmaxf(acc.x + b.x, 0.0f);
    float oy = fmaxf(acc.y + b.y, 0.0f);
    float oz = fmaxf(acc.z + b.z, 0.0f);
    float ow = fmaxf(acc.w + b.w, 0.0f);
    uint32_t l01, h01 = split2(ox, oy, l01);
    uint32_t l23, h23 = split2(oz, ow, l23);
    size_t o = (size_t)i * C2 + c4 * 4;
    *(uint2*)(g_h2h + o) = make_uint2(h01, h23);
    *(uint2*)(g_h2l + o) = make_uint2(l01, l23);
}

// agg3 fused with mean-pool + tail-block classifier.
// block = (32, 8): 8 nodes, 32 threads x float4 = 128 dims. 50000 % 8 == 0.
__global__ void k_agg3pool(const float* __restrict__ m, const float* __restrict__ bias,
                           const int* __restrict__ batch, const float* __restrict__ Wc,
                           const float* __restrict__ bc, float* __restrict__ out) {
    __shared__ float4 sval[8][32];
    __shared__ int sgid[8];
    __shared__ bool is_last;
    int ty = threadIdx.y;
    int c4 = threadIdx.x;  // 0..31
    int i = blockIdx.x * 8 + ty;
    const float4* m4 = (const float4*)m;
    float d = g_dis[i];
    float dd = d * d;
    float4 v = m4[(size_t)i * (C3 / 4) + c4];
    float4 acc = make_float4(dd * v.x, dd * v.y, dd * v.z, dd * v.w);
    int e0 = g_off[i], e1 = g_off[i + 1];
    for (int e = e0; e < e1; e++) {
        int r = g_row[e];
        float w = g_nrm[e];
        float4 u = m4[(size_t)r * (C3 / 4) + c4];
        acc.x = fmaf(w, u.x, acc.x);
        acc.y = fmaf(w, u.y, acc.y);
        acc.z = fmaf(w, u.z, acc.z);
        acc.w = fmaf(w, u.w, acc.w);
    }
    float4 b = ((const float4*)bias)[c4];
    int g = batch[i];
    float wi = g_winv[g];
    float4 o;
    o.x = fmaxf(acc.x + b.x, 0.0f) * wi;
    o.y = fmaxf(acc.y + b.y, 0.0f) * wi;
    o.z = fmaxf(acc.z + b.z, 0.0f) * wi;
    o.w = fmaxf(acc.w + b.w, 0.0f) * wi;
    sval[ty][c4] = o;
    if (c4 == 0) sgid[ty] = g;
    __syncthreads();
    if (ty == 0) {
        float4 run = make_float4(0.f, 0.f, 0.f, 0.f);
        int curg = sgid[0];
#pragma unroll
        for (int k = 0; k < 8; k++) {
            int gg = sgid[k];
            if (gg != curg) {
                float* p = g_pool + curg * C3 + c4 * 4;
                atomicAdd(p + 0, run.x);
                atomicAdd(p + 1, run.y);
                atomicAdd(p + 2, run.z);
                atomicAdd(p + 3, run.w);
                run = make_float4(0.f, 0.f, 0.f, 0.f);
                curg = gg;
            }
            float4 s = sval[k][c4];
            run.x += s.x; run.y += s.y; run.z += s.z; run.w += s.w;
        }
        float* p = g_pool + curg * C3 + c4 * 4;
        atomicAdd(p + 0, run.x);
        atomicAdd(p + 1, run.y);
        atomicAdd(p + 2, run.z);
        atomicAdd(p + 3, run.w);
    }
    // ---- tail-block classifier ----
    __threadfence();
    __syncthreads();
    if (ty == 0 && c4 == 0) {
        unsigned int vdone = atomicAdd(&g_done, 1u);
        is_last = (vdone == gridDim.x - 1);
        if (is_last) g_done = 0;  // reset for next replay
    }
    __syncthreads();
    if (is_last) {
        __threadfence();
        int gg = ty * 32 + c4;  // 0..255
        if (gg < NGRAPH) {
            float l0 = bc[0], l1 = bc[1];
#pragma unroll 4
            for (int c = 0; c < C3; c++) {
                float p = g_pool[gg * C3 + c];
                l0 = fmaf(p, Wc[c * 2 + 0], l0);
                l1 = fmaf(p, Wc[c * 2 + 1], l1);
            }
            float mx = fmaxf(l0, l1);
            float lse = mx + logf(expf(l0 - mx) + expf(l1 - mx));
            out[gg * 2 + 0] = l0 - lse;
            out[gg * 2 + 1] = l1 - lse;
        }
    }
}

// ------------------------- launch -------------------------
extern "C" void kernel_launch(void* const* d_in, const int* in_sizes, int n_in,
                              void* d_out, int out_size) {
    const float* x  = (const float*)d_in[0];
    const float* W1 = (const float*)d_in[1];
    const float* b1 = (const float*)d_in[2];
    const float* W2 = (const float*)d_in[3];
    const float* b2 = (const float*)d_in[4];
    const float* W3 = (const float*)d_in[5];
    const float* b3 = (const float*)d_in[6];
    const float* Wc = (const float*)d_in[7];
    const float* bc = (const float*)d_in[8];
    // JAX default config: x64 disabled -> "int64" arrays are int32.
    const int* ei    = (const int*)d_in[9];
    const int* batch = (const int*)d_in[10];
    float* out = (float*)d_out;

    float *g_aggx_p, *g_m2_p, *g_m3_p;
    __nv_bfloat16 *w2h_p, *w2l_p, *w3h_p, *w3l_p, *h2h_p, *h2l_p;
    cudaGetSymbolAddress((void**)&g_aggx_p, g_aggx);
    cudaGetSymbolAddress((void**)&g_m2_p, g_m2);
    cudaGetSymbolAddress((void**)&g_m3_p, g_m3);
    cudaGetSymbolAddress((void**)&w2h_p, g_Wt2h);
    cudaGetSymbolAddress((void**)&w2l_p, g_Wt2l);
    cudaGetSymbolAddress((void**)&w3h_p, g_Wt3h);
    cudaGetSymbolAddress((void**)&w3l_p, g_Wt3l);
    cudaGetSymbolAddress((void**)&h2h_p, g_h2h);
    cudaGetSymbolAddress((void**)&h2l_p, g_h2l);

    static bool init_done = false;
    static cudaStream_t s2;
    static cudaEvent_t ev1, ev2;
    if (!init_done) {
        cudaFuncSetAttribute((const void*)k_gemm_mma<C1, C2, true>,
                             cudaFuncAttributeMaxDynamicSharedMemorySize, SMEM_G2);
        cudaFuncSetAttribute((const void*)k_gemm_mma<C2, C3, false>,
                             cudaFuncAttributeMaxDynamicSharedMemorySize, SMEM_G3);
        cudaStreamCreateWithFlags(&s2, cudaStreamNonBlocking);
        cudaEventCreateWithFlags(&ev1, cudaEventDisableTiming);
        cudaEventCreateWithFlags(&ev2, cudaEventDisableTiming);
        init_done = true;
    }

    // fork: prep runs on s2 concurrent with CSR build
    cudaEventRecord(ev1, 0);
    cudaStreamWaitEvent(s2, ev1, 0);
    k_prep<<<(C1 * C2 + C2 * C3 + 255) / 256, 256, 0, s2>>>(W2, W3, batch);
    cudaEventRecord(ev2, s2);

    // CSR build (main stream)
    k_zero<<<(N_NODES + 255) / 256, 256>>>();
    k_count<<<(N_EDGES + 255) / 256, 256>>>(ei);
    k_scan<<<SCAN_BLOCKS, SCAN_TILE>>>(x);       // + dis + cur zero + aggx self-loop
    k_fill<<<(N_EDGES + 255) / 256, 256>>>(ei, x);  // + edge-parallel aggx atomics

    // join: GEMM2 needs prepped weights (and agg3pool needs g_winv/g_pool)
    cudaStreamWaitEvent(0, ev2, 0);

    // fused layer1 + GEMM2 on HMMA tensor cores: m2 = relu(aggx@W1+b1) @ W2
    k_gemm_mma<C1, C2, true><<<dim3(C2 / 64, NBLK), 256, SMEM_G2>>>(
        g_aggx_p, W1, b1, nullptr, nullptr, w2h_p, w2l_p, g_m2_p);
    k_agg2<<<(N_NODES + 3) / 4, dim3(C2 / 4, 4)>>>(g_m2_p, b2);

    // GEMM3: m3 = h2 @ W3
    k_gemm_mma<C2, C3, false><<<dim3(C3 / 64, NBLK), 256, SMEM_G3>>>(
        nullptr, nullptr, nullptr, h2h_p, h2l_p, w3h_p, w3l_p, g_m3_p);

    // agg3 + mean pool + tail-block classifier
    k_agg3pool<<<N_NODES / 8, dim3(C3 / 4, 8)>>>(g_m3_p, b3, batch, Wc, bc, out);
}

// round 12
// speedup vs baseline: 1.0586x; 1.0586x over previous
#include <cuda_runtime.h>
#include <cuda_bf16.h>
#include <math.h>
#include <stdint.h>

#define N_NODES 50000
#define N_EDGES 800000
#define C1 512
#define C2 256
#define C3 128
#define NGRAPH 100
#define NBLK ((N_NODES + 127) / 128)   // 391
#define NPAD (NBLK * 128)              // 50048

#define SCAN_TILE 256
#define SCAN_BLOCKS ((N_NODES + SCAN_TILE - 1) / SCAN_TILE)  // 196

// ------------------------- helpers -------------------------
__device__ __forceinline__ uint32_t smem_u32(const void* p) {
    uint32_t a;
    asm("{ .reg .u64 t; cvta.to.shared.u64 t, %1; cvt.u32.u64 %0, t; }" : "=r"(a) : "l"(p));
    return a;
}
__device__ __forceinline__ uint32_t sw128(uint32_t o) { return o ^ ((o >> 3) & 0x70); }

__device__ __forceinline__ uint32_t split2(float v0, float v1, uint32_t& lo_out) {
    __nv_bfloat16 h0 = __float2bfloat16(v0);
    __nv_bfloat16 h1 = __float2bfloat16(v1);
    __nv_bfloat16 l0 = __float2bfloat16(v0 - __bfloat162float(h0));
    __nv_bfloat16 l1 = __float2bfloat16(v1 - __bfloat162float(h1));
    __nv_bfloat162 hp = __halves2bfloat162(h0, h1);
    __nv_bfloat162 lp = __halves2bfloat162(l0, l1);
    lo_out = *reinterpret_cast<uint32_t*>(&lp);
    return *reinterpret_cast<uint32_t*>(&hp);
}

__device__ __forceinline__ void ldsm4(uint32_t* r, uint32_t addr) {
    asm volatile("ldmatrix.sync.aligned.m8n8.x4.shared.b16 {%0,%1,%2,%3}, [%4];"
                 : "=r"(r[0]), "=r"(r[1]), "=r"(r[2]), "=r"(r[3]) : "r"(addr));
}

__device__ __forceinline__ void mma_bf16(float* c, const uint32_t* a, const uint32_t* b) {
    asm volatile(
        "mma.sync.aligned.m16n8k16.row.col.f32.bf16.bf16.f32 "
        "{%0,%1,%2,%3}, {%4,%5,%6,%7}, {%8,%9}, {%0,%1,%2,%3};"
        : "+f"(c[0]), "+f"(c[1]), "+f"(c[2]), "+f"(c[3])
        : "r"(a[0]), "r"(a[1]), "r"(a[2]), "r"(a[3]), "r"(b[0]), "r"(b[1]));
}

// ------------------------- scratch (device globals) -------------------------
// NOTE: g_cnt/g_state are zeroed by module-load init on run 1, then re-zeroed
// by k_cls at the END of each run for the next graph replay.
__device__ int   g_cnt[N_NODES];
__device__ int   g_cur[N_NODES];
__device__ int   g_off[N_NODES + 1];
__device__ unsigned int g_state[SCAN_BLOCKS];   // lookback state: bit30 agg, bit31 prefix
__device__ float g_dis[N_NODES];
__device__ int   g_row[N_EDGES];
__device__ float g_nrm[N_EDGES];

__device__ __align__(16) float g_aggx[N_NODES * 3];
__device__ __align__(16) float g_m2[(size_t)N_NODES * C2];
__device__ __align__(16) float g_m3[(size_t)N_NODES * C3];
__device__ __align__(16) float g_pool[NGRAPH * C3];
__device__ float g_winv[NGRAPH];

// bf16 split weights (transposed to [N][K]) and h2 splits
__device__ __align__(16) __nv_bfloat16 g_Wt2h[C2 * C1];
__device__ __align__(16) __nv_bfloat16 g_Wt2l[C2 * C1];
__device__ __align__(16) __nv_bfloat16 g_Wt3h[C3 * C2];
__device__ __align__(16) __nv_bfloat16 g_Wt3l[C3 * C2];
__device__ __align__(16) __nv_bfloat16 g_h2h[(size_t)NPAD * C2];  // pad rows stay zero
__device__ __align__(16) __nv_bfloat16 g_h2l[(size_t)NPAD * C2];

// ------------------------- CSR build -------------------------
__global__ void k_count(const int* __restrict__ ei) {
    int e = blockIdx.x * blockDim.x + threadIdx.x;
    if (e < N_EDGES) atomicAdd(&g_cnt[ei[N_EDGES + e]], 1);
}

// single-pass scan with decoupled lookback (+ dis + g_cur zero fused)
__global__ void k_scan() {
    __shared__ int sm[SCAN_TILE];
    __shared__ int sprefix;
    int tid = threadIdx.x;
    int b = blockIdx.x;
    int i = b * SCAN_TILE + tid;
    int v = 0;
    if (i < N_NODES) {
        v = g_cnt[i];
        g_dis[i] = rsqrtf((float)(v + 1));  // +1 self-loop
        g_cur[i] = 0;
    }
    sm[tid] = v;
    __syncthreads();
#pragma unroll
    for (int ofs = 1; ofs < SCAN_TILE; ofs <<= 1) {
        int t = (tid >= ofs) ? sm[tid - ofs] : 0;
        __syncthreads();
        sm[tid] += t;
        __syncthreads();
    }
    if (tid == 0) {
        unsigned int total = (unsigned int)sm[SCAN_TILE - 1];
        atomicExch(&g_state[b], (1u << 30) | total);  // aggregate ready
        unsigned int ex = 0;
        for (int j = b - 1; j >= 0; j--) {
            unsigned int s;
            do { s = atomicAdd(&g_state[j], 0u); } while (s == 0u);
            ex += s & 0x3FFFFFFFu;
            if (s & (1u << 31)) break;  // inclusive prefix available
        }
        atomicExch(&g_state[b], (1u << 31) | (ex + total));  // prefix ready
        sprefix = (int)ex;
    }
    __syncthreads();
    if (i < N_NODES) g_off[i + 1] = sprefix + sm[tid];
    if (b == 0 && tid == 0) g_off[0] = 0;
}

__global__ void k_fill(const int* __restrict__ ei) {
    int e = blockIdx.x * blockDim.x + threadIdx.x;
    if (e < N_EDGES) {
        int row = ei[e];
        int col = ei[N_EDGES + e];
        int pos = g_off[col] + atomicAdd(&g_cur[col], 1);
        g_row[pos] = row;
        g_nrm[pos] = g_dis[row] * g_dis[col];
    }
}

// ------------------------- side-stream prep: weight split + graph counts + pool zero -----
__global__ void k_prep(const float* __restrict__ W2, const float* __restrict__ W3,
                       const int* __restrict__ batch) {
    int idx = blockIdx.x * 256 + threadIdx.x;
    if (idx < C1 * C2) {
        int n = idx / C1, k = idx % C1;
        float v = W2[(size_t)k * C2 + n];
        __nv_bfloat16 h = __float2bfloat16(v);
        g_Wt2h[idx] = h;
        g_Wt2l[idx] = __float2bfloat16(v - __bfloat162float(h));
    }
    int idx3 = idx - C1 * C2;
    if (idx3 >= 0 && idx3 < C2 * C3) {
        int n = idx3 / C2, k = idx3 % C2;
        float v = W3[(size_t)k * C3 + n];
        __nv_bfloat16 h = __float2bfloat16(v);
        g_Wt3h[idx3] = h;
        g_Wt3l[idx3] = __float2bfloat16(v - __bfloat162float(h));
    }
    if (idx < NGRAPH * C3) g_pool[idx] = 0.0f;
    if (idx < NGRAPH) {
        // count nodes with batch == idx (batch sorted)
        int lo = 0, hi = N_NODES;
        while (lo < hi) { int m = (lo + hi) >> 1; if (batch[m] < idx) lo = m + 1; else hi = m; }
        int s = lo;
        lo = 0; hi = N_NODES;
        while (lo < hi) { int m = (lo + hi) >> 1; if (batch[m] < idx + 1) lo = m + 1; else hi = m; }
        int cnt = lo - s;
        g_winv[idx] = 1.0f / (float)(cnt > 0 ? cnt : 1);
    }
}

// ------------------------- layer 1 aggregate (3 dims) -------------------------
__global__ void k_aggx(const float* __restrict__ x) {
    int i = blockIdx.x * blockDim.x + threadIdx.x;
    if (i >= N_NODES) return;
    float d = g_dis[i];
    float dd = d * d;
    float a0 = dd * x[i * 3 + 0];
    float a1 = dd * x[i * 3 + 1];
    float a2 = dd * x[i * 3 + 2];
    int e0 = g_off[i], e1 = g_off[i + 1];
    for (int e = e0; e < e1; e++) {
        int r = g_row[e];
        float w = g_nrm[e];
        a0 += w * x[r * 3 + 0];
        a1 += w * x[r * 3 + 1];
        a2 += w * x[r * 3 + 2];
    }
    g_aggx[i * 3 + 0] = a0;
    g_aggx[i * 3 + 1] = a1;
    g_aggx[i * 3 + 2] = a2;
}

// ===================== HMMA split-bf16 GEMM (single-buffered — R7 form) =====================
// Inter-CTA overlap (2 CTAs/SM) hides the fill phase; intra-CTA double-buffering
// measured WORSE (R8: +20us) — do not reintroduce.

#define G2_B1  0
#define G2_W1  2048
#define G2_AX  8192
#define G2_AHI 10240
#define G2_ALO 26624
#define G2_BHI 43008
#define G2_BLO 51200
#define SMEM_G2 59392
#define G3_AHI 0
#define G3_ALO 16384
#define G3_BHI 32768
#define G3_BLO 40960
#define SMEM_G3 49152

template <int K, int NTOT, bool GENA>
__global__ __launch_bounds__(256) void k_gemm_mma(
    const float* __restrict__ aggx, const float* __restrict__ W1,
    const float* __restrict__ b1,
    const __nv_bfloat16* __restrict__ Agh, const __nv_bfloat16* __restrict__ Agl,
    const __nv_bfloat16* __restrict__ Bgh, const __nv_bfloat16* __restrict__ Bgl,
    float* __restrict__ Cout) {
    extern __shared__ char smem[];
    const uint32_t sb = smem_u32(smem);
    const int tid = threadIdx.x;
    const int lane = tid & 31;
    const int wid = tid >> 5;
    const int wm = wid >> 1;
    const int wn = wid & 1;
    const int rowBase = blockIdx.y * 128;
    const int colBase = blockIdx.x * 64;

    constexpr int OAH = GENA ? G2_AHI : G3_AHI;
    constexpr int OAL = GENA ? G2_ALO : G3_ALO;
    constexpr int OBH = GENA ? G2_BHI : G3_BHI;
    constexpr int OBL = GENA ? G2_BLO : G3_BLO;

    float* b1s = (float*)(smem + G2_B1);
    float* W1s = (float*)(smem + G2_W1);
    float(*ax)[4] = (float(*)[4])(smem + G2_AX);

    if constexpr (GENA) {
        for (int i = tid; i < C1; i += 256) b1s[i] = b1[i];
        for (int i = tid; i < 3 * C1; i += 256) W1s[i] = W1[i];
        for (int i = tid; i < 128 * 3; i += 256) {
            int r = i / 3, j = i % 3;
            int gr = rowBase + r;
            ax[r][j] = (gr < N_NODES) ? aggx[gr * 3 + j] : 0.0f;
        }
        __syncthreads();
    }

    float acc[2][4][4];
#pragma unroll
    for (int mt = 0; mt < 2; mt++)
#pragma unroll
        for (int nt = 0; nt < 4; nt++)
#pragma unroll
            for (int j = 0; j < 4; j++) acc[mt][nt][j] = 0.0f;

    const int quad = lane >> 3;
    const int lr = lane & 7;

    for (int k0 = 0; k0 < K; k0 += 64) {
        if constexpr (GENA) {
            const int kp = tid & 31;
            const int rg = tid >> 5;
            const int k = k0 + kp * 2;
            const float w0a = W1s[k], w0b = W1s[k + 1];
            const float w1a = W1s[C1 + k], w1b = W1s[C1 + k + 1];
            const float w2a = W1s[2 * C1 + k], w2b = W1s[2 * C1 + k + 1];
            const float ba = b1s[k], bb = b1s[k + 1];
#pragma unroll 4
            for (int rr = 0; rr < 16; rr++) {
                int r = rg * 16 + rr;
                float a0 = ax[r][0], a1 = ax[r][1], a2 = ax[r][2];
                float v0 = fmaxf(ba + a0 * w0a + a1 * w1a + a2 * w2a, 0.0f);
                float v1 = fmaxf(bb + a0 * w0b + a1 * w1b + a2 * w2b, 0.0f);
                if (rowBase + r >= N_NODES) { v0 = 0.0f; v1 = 0.0f; }
                uint32_t lw, hw = split2(v0, v1, lw);
                uint32_t so = sw128((uint32_t)(r * 128 + kp * 4));
                *(uint32_t*)(smem + OAH + so) = hw;
                *(uint32_t*)(smem + OAL + so) = lw;
            }
        } else {
#pragma unroll
            for (int i = 0; i < 4; i++) {
                int idx = tid + 256 * i;
                int r = idx >> 3, ch = idx & 7;
                size_t src = (size_t)(rowBase + r) * K + k0 + ch * 8;
                uint4 vh = *(const uint4*)(Agh + src);
                uint4 vl = *(const uint4*)(Agl + src);
                uint32_t so = sw128((uint32_t)(r * 128 + ch * 16));
                *(uint4*)(smem + OAH + so) = vh;
                *(uint4*)(smem + OAL + so) = vl;
            }
        }
#pragma unroll
        for (int i = 0; i < 2; i++) {
            int idx = tid + 256 * i;
            int n = idx >> 3, ch = idx & 7;
            size_t src = (size_t)(colBase + n) * K + k0 + ch * 8;
            uint4 vh = *(const uint4*)(Bgh + src);
            uint4 vl = *(const uint4*)(Bgl + src);
            uint32_t so = sw128((uint32_t)(n * 128 + ch * 16));
            *(uint4*)(smem + OBH + so) = vh;
            *(uint4*)(smem + OBL + so) = vl;
        }
        __syncthreads();

#pragma unroll
        for (int ks = 0; ks < 4; ks++) {
            uint32_t ahi[2][4], alo[2][4];
#pragma unroll
            for (int mt = 0; mt < 2; mt++) {
                int row = wm * 32 + mt * 16 + (quad & 1) * 8 + lr;
                uint32_t kb = ks * 32 + (quad >> 1) * 16;
                uint32_t so = sw128((uint32_t)(row * 128) + kb);
                ldsm4(ahi[mt], sb + OAH + so);
                ldsm4(alo[mt], sb + OAL + so);
            }
            uint32_t bhi[4][2], blo[4][2];
#pragma unroll
            for (int p = 0; p < 2; p++) {
                int n = wn * 32 + p * 16 + (quad >> 1) * 8 + lr;
                uint32_t kb = ks * 32 + (quad & 1) * 16;
                uint32_t so = sw128((uint32_t)(n * 128) + kb);
                uint32_t rh[4], rl[4];
                ldsm4(rh, sb + OBH + so);
                ldsm4(rl, sb + OBL + so);
                bhi[p * 2][0] = rh[0]; bhi[p * 2][1] = rh[1];
                bhi[p * 2 + 1][0] = rh[2]; bhi[p * 2 + 1][1] = rh[3];
                blo[p * 2][0] = rl[0]; blo[p * 2][1] = rl[1];
                blo[p * 2 + 1][0] = rl[2]; blo[p * 2 + 1][1] = rl[3];
            }
#pragma unroll
            for (int mt = 0; mt < 2; mt++)
#pragma unroll
                for (int nt = 0; nt < 4; nt++) {
                    mma_bf16(acc[mt][nt], ahi[mt], bhi[nt]);
                    mma_bf16(acc[mt][nt], ahi[mt], blo[nt]);
                    mma_bf16(acc[mt][nt], alo[mt], bhi[nt]);
                }
        }
        __syncthreads();
    }

#pragma unroll
    for (int mt = 0; mt < 2; mt++) {
        int r0 = rowBase + wm * 32 + mt * 16 + (lane >> 2);
        int r1 = r0 + 8;
#pragma unroll
        for (int nt = 0; nt < 4; nt++) {
            int c = colBase + wn * 32 + nt * 8 + (lane & 3) * 2;
            if (r0 < N_NODES)
                *(float2*)(Cout + (size_t)r0 * NTOT + c) = make_float2(acc[mt][nt][0], acc[mt][nt][1]);
            if (r1 < N_NODES)
                *(float2*)(Cout + (size_t)r1 * NTOT + c) = make_float2(acc[mt][nt][2], acc[mt][nt][3]);
        }
    }
}

// ------------------------- CSR aggregation -------------------------
// agg2: h2 = relu(Anorm @ m2 + b2), output split to bf16 hi/lo
__global__ void k_agg2(const float* __restrict__ m, const float* __restrict__ bias) {
    int i = blockIdx.x * 4 + threadIdx.y;
    if (i >= N_NODES) return;
    int c4 = threadIdx.x;  // 0..63
    const float4* m4 = (const float4*)m;
    float d = g_dis[i];
    float dd = d * d;
    float4 v = m4[(size_t)i * (C2 / 4) + c4];
    float4 acc = make_float4(dd * v.x, dd * v.y, dd * v.z, dd * v.w);
    int e0 = g_off[i], e1 = g_off[i + 1];
    for (int e = e0; e < e1; e++) {
        int r = g_row[e];
        float w = g_nrm[e];
        float4 u = m4[(size_t)r * (C2 / 4) + c4];
        acc.x = fmaf(w, u.x, acc.x);
        acc.y = fmaf(w, u.y, acc.y);
        acc.z = fmaf(w, u.z, acc.z);
        acc.w = fmaf(w, u.w, acc.w);
    }
    float4 b = ((const float4*)bias)[c4];
    float ox = fmaxf(acc.x + b.x, 0.0f);
    float oy = fmaxf(acc.y + b.y, 0.0f);
    float oz = fmaxf(acc.z + b.z, 0.0f);
    float ow = fmaxf(acc.w + b.w, 0.0f);
    uint32_t l01, h01 = split2(ox, oy, l01);
    uint32_t l23, h23 = split2(oz, ow, l23);
    size_t o = (size_t)i * C2 + c4 * 4;
    *(uint2*)(g_h2h + o) = make_uint2(h01, h23);
    *(uint2*)(g_h2l + o) = make_uint2(l01, l23);
}

// agg3 fused with mean-pool: pool[batch[i]] += relu(Anorm@m3+b3)[i] * winv[batch[i]]
// block = (32, 8): 8 nodes, 32 threads x float4 = 128 dims. 50000 % 8 == 0.
__global__ void k_agg3pool(const float* __restrict__ m, const float* __restrict__ bias,
                           const int* __restrict__ batch) {
    __shared__ float4 sval[8][32];
    __shared__ int sgid[8];
    int ty = threadIdx.y;
    int c4 = threadIdx.x;  // 0..31
    int i = blockIdx.x * 8 + ty;
    const float4* m4 = (const float4*)m;
    float d = g_dis[i];
    float dd = d * d;
    float4 v = m4[(size_t)i * (C3 / 4) + c4];
    float4 acc = make_float4(dd * v.x, dd * v.y, dd * v.z, dd * v.w);
    int e0 = g_off[i], e1 = g_off[i + 1];
    for (int e = e0; e < e1; e++) {
        int r = g_row[e];
        float w = g_nrm[e];
        float4 u = m4[(size_t)r * (C3 / 4) + c4];
        acc.x = fmaf(w, u.x, acc.x);
        acc.y = fmaf(w, u.y, acc.y);
        acc.z = fmaf(w, u.z, acc.z);
        acc.w = fmaf(w, u.w, acc.w);
    }
    float4 b = ((const float4*)bias)[c4];
    int g = batch[i];
    float wi = g_winv[g];
    float4 o;
    o.x = fmaxf(acc.x + b.x, 0.0f) * wi;
    o.y = fmaxf(acc.y + b.y, 0.0f) * wi;
    o.z = fmaxf(acc.z + b.z, 0.0f) * wi;
    o.w = fmaxf(acc.w + b.w, 0.0f) * wi;
    sval[ty][c4] = o;
    if (c4 == 0) sgid[ty] = g;
    __syncthreads();
    if (ty == 0) {
        // segment-reduce the 8 nodes by graph id (sorted), one atomic set per segment
        float4 run = make_float4(0.f, 0.f, 0.f, 0.f);
        int curg = sgid[0];
#pragma unroll
        for (int k = 0; k < 8; k++) {
            int gg = sgid[k];
            if (gg != curg) {
                float* p = g_pool + curg * C3 + c4 * 4;
                atomicAdd(p + 0, run.x);
                atomicAdd(p + 1, run.y);
                atomicAdd(p + 2, run.z);
                atomicAdd(p + 3, run.w);
                run = make_float4(0.f, 0.f, 0.f, 0.f);
                curg = gg;
            }
            float4 s = sval[k][c4];
            run.x += s.x; run.y += s.y; run.z += s.z; run.w += s.w;
        }
        float* p = g_pool + curg * C3 + c4 * 4;
        atomicAdd(p + 0, run.x);
        atomicAdd(p + 1, run.y);
        atomicAdd(p + 2, run.z);
        atomicAdd(p + 3, run.w);
    }
}

// ------------------------- classifier + next-replay counter reset -------------------------
// grid = 98 x 512 threads: block 0 computes the classifier; ALL blocks zero
// g_cnt/g_state for the NEXT graph replay (module-load init covers run 1).
__global__ void k_cls(const float* __restrict__ Wc, const float* __restrict__ bc,
                      float* __restrict__ out) {
    int tid = threadIdx.x;
    int idx = blockIdx.x * 512 + tid;
    if (idx < N_NODES) g_cnt[idx] = 0;
    if (idx < SCAN_BLOCKS) g_state[idx] = 0u;
    if (blockIdx.x == 0 && tid < NGRAPH) {
        int g = tid;
        float l0 = bc[0], l1 = bc[1];
        for (int c = 0; c < C3; c++) {
            float p = g_pool[g * C3 + c];
            l0 = fmaf(p, Wc[c * 2 + 0], l0);
            l1 = fmaf(p, Wc[c * 2 + 1], l1);
        }
        float mx = fmaxf(l0, l1);
        float lse = mx + logf(expf(l0 - mx) + expf(l1 - mx));
        out[g * 2 + 0] = l0 - lse;
        out[g * 2 + 1] = l1 - lse;
    }
}

// ------------------------- launch -------------------------
extern "C" void kernel_launch(void* const* d_in, const int* in_sizes, int n_in,
                              void* d_out, int out_size) {
    const float* x  = (const float*)d_in[0];
    const float* W1 = (const float*)d_in[1];
    const float* b1 = (const float*)d_in[2];
    const float* W2 = (const float*)d_in[3];
    const float* b2 = (const float*)d_in[4];
    const float* W3 = (const float*)d_in[5];
    const float* b3 = (const float*)d_in[6];
    const float* Wc = (const float*)d_in[7];
    const float* bc = (const float*)d_in[8];
    // JAX default config: x64 disabled -> "int64" arrays are int32.
    const int* ei    = (const int*)d_in[9];
    const int* batch = (const int*)d_in[10];
    float* out = (float*)d_out;

    float *g_aggx_p, *g_m2_p, *g_m3_p;
    __nv_bfloat16 *w2h_p, *w2l_p, *w3h_p, *w3l_p, *h2h_p, *h2l_p;
    cudaGetSymbolAddress((void**)&g_aggx_p, g_aggx);
    cudaGetSymbolAddress((void**)&g_m2_p, g_m2);
    cudaGetSymbolAddress((void**)&g_m3_p, g_m3);
    cudaGetSymbolAddress((void**)&w2h_p, g_Wt2h);
    cudaGetSymbolAddress((void**)&w2l_p, g_Wt2l);
    cudaGetSymbolAddress((void**)&w3h_p, g_Wt3h);
    cudaGetSymbolAddress((void**)&w3l_p, g_Wt3l);
    cudaGetSymbolAddress((void**)&h2h_p, g_h2h);
    cudaGetSymbolAddress((void**)&h2l_p, g_h2l);

    static bool init_done = false;
    static cudaStream_t s2;
    static cudaEvent_t ev1, ev2;
    if (!init_done) {
        cudaFuncSetAttribute((const void*)k_gemm_mma<C1, C2, true>,
                             cudaFuncAttributeMaxDynamicSharedMemorySize, SMEM_G2);
        cudaFuncSetAttribute((const void*)k_gemm_mma<C2, C3, false>,
                             cudaFuncAttributeMaxDynamicSharedMemorySize, SMEM_G3);
        cudaStreamCreateWithFlags(&s2, cudaStreamNonBlocking);
        cudaEventCreateWithFlags(&ev1, cudaEventDisableTiming);
        cudaEventCreateWithFlags(&ev2, cudaEventDisableTiming);
        init_done = true;
    }

    // fork: prep runs on s2 concurrent with CSR build
    cudaEventRecord(ev1, 0);
    cudaStreamWaitEvent(s2, ev1, 0);
    k_prep<<<(C1 * C2 + C2 * C3 + 255) / 256, 256, 0, s2>>>(W2, W3, batch);
    cudaEventRecord(ev2, s2);

    // CSR build (main stream). g_cnt/g_state pre-zeroed (module init / previous k_cls).
    k_count<<<(N_EDGES + 255) / 256, 256>>>(ei);
    k_scan<<<SCAN_BLOCKS, SCAN_TILE>>>();        // single-pass lookback + dis + cur zero
    k_fill<<<(N_EDGES + 255) / 256, 256>>>(ei);
    k_aggx<<<(N_NODES + 255) / 256, 256>>>(x);

    // join: GEMM2 needs prepped weights (and agg3pool needs g_winv/g_pool)
    cudaStreamWaitEvent(0, ev2, 0);

    // fused layer1 + GEMM2 on HMMA tensor cores: m2 = relu(aggx@W1+b1) @ W2
    k_gemm_mma<C1, C2, true><<<dim3(C2 / 64, NBLK), 256, SMEM_G2>>>(
        g_aggx_p, W1, b1, nullptr, nullptr, w2h_p, w2l_p, g_m2_p);
    k_agg2<<<(N_NODES + 3) / 4, dim3(C2 / 4, 4)>>>(g_m2_p, b2);

    // GEMM3: m3 = h2 @ W3
    k_gemm_mma<C2, C3, false><<<dim3(C3 / 64, NBLK), 256, SMEM_G3>>>(
        nullptr, nullptr, nullptr, h2h_p, h2l_p, w3h_p, w3l_p, g_m3_p);

    // agg3 fused with mean pool (atomic segmented reduction)
    k_agg3pool<<<N_NODES / 8, dim3(C3 / 4, 8)>>>(g_m3_p, b3, batch);

    // classifier + zero counters for next replay
    k_cls<<<98, 512>>>(Wc, bc, out);
}

// round 13
// speedup vs baseline: 1.0651x; 1.0062x over previous
#include <cuda_runtime.h>
#include <cuda_bf16.h>
#include <math.h>
#include <stdint.h>

#define N_NODES 50000
#define N_EDGES 800000
#define C1 512
#define C2 256
#define C3 128
#define NGRAPH 100
#define NBLK ((N_NODES + 127) / 128)   // 391
#define NPAD (NBLK * 128)              // 50048

#define SCAN_TILE 256
#define SCAN_BLOCKS ((N_NODES + SCAN_TILE - 1) / SCAN_TILE)  // 196

// ------------------------- helpers -------------------------
__device__ __forceinline__ uint32_t smem_u32(const void* p) {
    uint32_t a;
    asm("{ .reg .u64 t; cvta.to.shared.u64 t, %1; cvt.u32.u64 %0, t; }" : "=r"(a) : "l"(p));
    return a;
}
__device__ __forceinline__ uint32_t sw128(uint32_t o) { return o ^ ((o >> 3) & 0x70); }

__device__ __forceinline__ uint32_t split2(float v0, float v1, uint32_t& lo_out) {
    __nv_bfloat16 h0 = __float2bfloat16(v0);
    __nv_bfloat16 h1 = __float2bfloat16(v1);
    __nv_bfloat16 l0 = __float2bfloat16(v0 - __bfloat162float(h0));
    __nv_bfloat16 l1 = __float2bfloat16(v1 - __bfloat162float(h1));
    __nv_bfloat162 hp = __halves2bfloat162(h0, h1);
    __nv_bfloat162 lp = __halves2bfloat162(l0, l1);
    lo_out = *reinterpret_cast<uint32_t*>(&lp);
    return *reinterpret_cast<uint32_t*>(&hp);
}

__device__ __forceinline__ void ldsm4(uint32_t* r, uint32_t addr) {
    asm volatile("ldmatrix.sync.aligned.m8n8.x4.shared.b16 {%0,%1,%2,%3}, [%4];"
                 : "=r"(r[0]), "=r"(r[1]), "=r"(r[2]), "=r"(r[3]) : "r"(addr));
}

__device__ __forceinline__ void mma_bf16(float* c, const uint32_t* a, const uint32_t* b) {
    asm volatile(
        "mma.sync.aligned.m16n8k16.row.col.f32.bf16.bf16.f32 "
        "{%0,%1,%2,%3}, {%4,%5,%6,%7}, {%8,%9}, {%0,%1,%2,%3};"
        : "+f"(c[0]), "+f"(c[1]), "+f"(c[2]), "+f"(c[3])
        : "r"(a[0]), "r"(a[1]), "r"(a[2]), "r"(a[3]), "r"(b[0]), "r"(b[1]));
}

// ------------------------- scratch (device globals) -------------------------
// NOTE: g_cnt/g_state are zeroed by module-load init on run 1, then re-zeroed
// by k_cls at the END of each run for the next graph replay.
__device__ int   g_cnt[N_NODES];
__device__ int   g_cur[N_NODES];     // pre-biased to segment start by k_scan
__device__ int   g_off[N_NODES + 1];
__device__ unsigned int g_state[SCAN_BLOCKS];   // lookback state: bit30 agg, bit31 prefix
__device__ float g_dis[N_NODES];
__device__ __align__(8) int2 g_edge[N_EDGES];   // {row, nrm-bits} interleaved

__device__ __align__(16) float g_aggx[N_NODES * 3];
__device__ __align__(16) float g_m2[(size_t)N_NODES * C2];
__device__ __align__(16) float g_m3[(size_t)N_NODES * C3];
__device__ __align__(16) float g_pool[NGRAPH * C3];
__device__ float g_winv[NGRAPH];

// bf16 split weights (transposed to [N][K]) and h2 splits
__device__ __align__(16) __nv_bfloat16 g_Wt2h[C2 * C1];
__device__ __align__(16) __nv_bfloat16 g_Wt2l[C2 * C1];
__device__ __align__(16) __nv_bfloat16 g_Wt3h[C3 * C2];
__device__ __align__(16) __nv_bfloat16 g_Wt3l[C3 * C2];
__device__ __align__(16) __nv_bfloat16 g_h2h[(size_t)NPAD * C2];  // pad rows stay zero
__device__ __align__(16) __nv_bfloat16 g_h2l[(size_t)NPAD * C2];

// ------------------------- CSR build -------------------------
__global__ void k_count(const int* __restrict__ ei) {
    int e = blockIdx.x * blockDim.x + threadIdx.x;
    if (e < N_EDGES) atomicAdd(&g_cnt[ei[N_EDGES + e]], 1);
}

// single-pass scan with decoupled lookback (+ dis + g_cur = segment-start)
__global__ void k_scan() {
    __shared__ int sm[SCAN_TILE];
    __shared__ int sprefix;
    int tid = threadIdx.x;
    int b = blockIdx.x;
    int i = b * SCAN_TILE + tid;
    int v = 0;
    if (i < N_NODES) {
        v = g_cnt[i];
        g_dis[i] = rsqrtf((float)(v + 1));  // +1 self-loop
    }
    sm[tid] = v;
    __syncthreads();
#pragma unroll
    for (int ofs = 1; ofs < SCAN_TILE; ofs <<= 1) {
        int t = (tid >= ofs) ? sm[tid - ofs] : 0;
        __syncthreads();
        sm[tid] += t;
        __syncthreads();
    }
    if (tid == 0) {
        unsigned int total = (unsigned int)sm[SCAN_TILE - 1];
        atomicExch(&g_state[b], (1u << 30) | total);  // aggregate ready
        unsigned int ex = 0;
        for (int j = b - 1; j >= 0; j--) {
            unsigned int s;
            do { s = atomicAdd(&g_state[j], 0u); } while (s == 0u);
            ex += s & 0x3FFFFFFFu;
            if (s & (1u << 31)) break;  // inclusive prefix available
        }
        atomicExch(&g_state[b], (1u << 31) | (ex + total));  // prefix ready
        sprefix = (int)ex;
    }
    __syncthreads();
    if (i < N_NODES) {
        int incl = sprefix + sm[tid];
        g_off[i + 1] = incl;
        g_cur[i] = incl - v;  // segment start: k_fill's atomicAdd returns absolute pos
    }
    if (b == 0 && tid == 0) g_off[0] = 0;
}

__global__ void k_fill(const int* __restrict__ ei) {
    int e = blockIdx.x * blockDim.x + threadIdx.x;
    if (e < N_EDGES) {
        int row = ei[e];
        int col = ei[N_EDGES + e];
        int pos = atomicAdd(&g_cur[col], 1);   // absolute position (pre-biased)
        float w = g_dis[row] * g_dis[col];
        g_edge[pos] = make_int2(row, __float_as_int(w));  // one 8B store
    }
}

// ------------------------- side-stream prep: weight split + graph counts + pool zero -----
__global__ void k_prep(const float* __restrict__ W2, const float* __restrict__ W3,
                       const int* __restrict__ batch) {
    int idx = blockIdx.x * 256 + threadIdx.x;
    if (idx < C1 * C2) {
        int n = idx / C1, k = idx % C1;
        float v = W2[(size_t)k * C2 + n];
        __nv_bfloat16 h = __float2bfloat16(v);
        g_Wt2h[idx] = h;
        g_Wt2l[idx] = __float2bfloat16(v - __bfloat162float(h));
    }
    int idx3 = idx - C1 * C2;
    if (idx3 >= 0 && idx3 < C2 * C3) {
        int n = idx3 / C2, k = idx3 % C2;
        float v = W3[(size_t)k * C3 + n];
        __nv_bfloat16 h = __float2bfloat16(v);
        g_Wt3h[idx3] = h;
        g_Wt3l[idx3] = __float2bfloat16(v - __bfloat162float(h));
    }
    if (idx < NGRAPH * C3) g_pool[idx] = 0.0f;
    if (idx < NGRAPH) {
        // count nodes with batch == idx (batch sorted)
        int lo = 0, hi = N_NODES;
        while (lo < hi) { int m = (lo + hi) >> 1; if (batch[m] < idx) lo = m + 1; else hi = m; }
        int s = lo;
        lo = 0; hi = N_NODES;
        while (lo < hi) { int m = (lo + hi) >> 1; if (batch[m] < idx + 1) lo = m + 1; else hi = m; }
        int cnt = lo - s;
        g_winv[idx] = 1.0f / (float)(cnt > 0 ? cnt : 1);
    }
}

// ------------------------- layer 1 aggregate (3 dims) -------------------------
__global__ void k_aggx(const float* __restrict__ x) {
    int i = blockIdx.x * blockDim.x + threadIdx.x;
    if (i >= N_NODES) return;
    float d = g_dis[i];
    float dd = d * d;
    float a0 = dd * x[i * 3 + 0];
    float a1 = dd * x[i * 3 + 1];
    float a2 = dd * x[i * 3 + 2];
    int e0 = g_off[i], e1 = g_off[i + 1];
    for (int e = e0; e < e1; e++) {
        int2 ed = g_edge[e];
        int r = ed.x;
        float w = __int_as_float(ed.y);
        a0 += w * x[r * 3 + 0];
        a1 += w * x[r * 3 + 1];
        a2 += w * x[r * 3 + 2];
    }
    g_aggx[i * 3 + 0] = a0;
    g_aggx[i * 3 + 1] = a1;
    g_aggx[i * 3 + 2] = a2;
}

// ===================== HMMA split-bf16 GEMM (single-buffered — R7 form) =====================
// Inter-CTA overlap (2 CTAs/SM) hides the fill phase; intra-CTA double-buffering
// measured WORSE (R8: +20us) — do not reintroduce.

#define G2_B1  0
#define G2_W1  2048
#define G2_AX  8192
#define G2_AHI 10240
#define G2_ALO 26624
#define G2_BHI 43008
#define G2_BLO 51200
#define SMEM_G2 59392
#define G3_AHI 0
#define G3_ALO 16384
#define G3_BHI 32768
#define G3_BLO 40960
#define SMEM_G3 49152

template <int K, int NTOT, bool GENA>
__global__ __launch_bounds__(256) void k_gemm_mma(
    const float* __restrict__ aggx, const float* __restrict__ W1,
    const float* __restrict__ b1,
    const __nv_bfloat16* __restrict__ Agh, const __nv_bfloat16* __restrict__ Agl,
    const __nv_bfloat16* __restrict__ Bgh, const __nv_bfloat16* __restrict__ Bgl,
    float* __restrict__ Cout) {
    extern __shared__ char smem[];
    const uint32_t sb = smem_u32(smem);
    const int tid = threadIdx.x;
    const int lane = tid & 31;
    const int wid = tid >> 5;
    const int wm = wid >> 1;
    const int wn = wid & 1;
    const int rowBase = blockIdx.y * 128;
    const int colBase = blockIdx.x * 64;

    constexpr int OAH = GENA ? G2_AHI : G3_AHI;
    constexpr int OAL = GENA ? G2_ALO : G3_ALO;
    constexpr int OBH = GENA ? G2_BHI : G3_BHI;
    constexpr int OBL = GENA ? G2_BLO : G3_BLO;

    float* b1s = (float*)(smem + G2_B1);
    float* W1s = (float*)(smem + G2_W1);
    float(*ax)[4] = (float(*)[4])(smem + G2_AX);

    if constexpr (GENA) {
        for (int i = tid; i < C1; i += 256) b1s[i] = b1[i];
        for (int i = tid; i < 3 * C1; i += 256) W1s[i] = W1[i];
        for (int i = tid; i < 128 * 3; i += 256) {
            int r = i / 3, j = i % 3;
            int gr = rowBase + r;
            ax[r][j] = (gr < N_NODES) ? aggx[gr * 3 + j] : 0.0f;
        }
        __syncthreads();
    }

    float acc[2][4][4];
#pragma unroll
    for (int mt = 0; mt < 2; mt++)
#pragma unroll
        for (int nt = 0; nt < 4; nt++)
#pragma unroll
            for (int j = 0; j < 4; j++) acc[mt][nt][j] = 0.0f;

    const int quad = lane >> 3;
    const int lr = lane & 7;

    for (int k0 = 0; k0 < K; k0 += 64) {
        if constexpr (GENA) {
            const int kp = tid & 31;
            const int rg = tid >> 5;
            const int k = k0 + kp * 2;
            const float w0a = W1s[k], w0b = W1s[k + 1];
            const float w1a = W1s[C1 + k], w1b = W1s[C1 + k + 1];
            const float w2a = W1s[2 * C1 + k], w2b = W1s[2 * C1 + k + 1];
            const float ba = b1s[k], bb = b1s[k + 1];
#pragma unroll 4
            for (int rr = 0; rr < 16; rr++) {
                int r = rg * 16 + rr;
                float a0 = ax[r][0], a1 = ax[r][1], a2 = ax[r][2];
                float v0 = fmaxf(ba + a0 * w0a + a1 * w1a + a2 * w2a, 0.0f);
                float v1 = fmaxf(bb + a0 * w0b + a1 * w1b + a2 * w2b, 0.0f);
                if (rowBase + r >= N_NODES) { v0 = 0.0f; v1 = 0.0f; }
                uint32_t lw, hw = split2(v0, v1, lw);
                uint32_t so = sw128((uint32_t)(r * 128 + kp * 4));
                *(uint32_t*)(smem + OAH + so) = hw;
                *(uint32_t*)(smem + OAL + so) = lw;
            }
        } else {
#pragma unroll
            for (int i = 0; i < 4; i++) {
                int idx = tid + 256 * i;
                int r = idx >> 3, ch = idx & 7;
                size_t src = (size_t)(rowBase + r) * K + k0 + ch * 8;
                uint4 vh = *(const uint4*)(Agh + src);
                uint4 vl = *(const uint4*)(Agl + src);
                uint32_t so = sw128((uint32_t)(r * 128 + ch * 16));
                *(uint4*)(smem + OAH + so) = vh;
                *(uint4*)(smem + OAL + so) = vl;
            }
        }
#pragma unroll
        for (int i = 0; i < 2; i++) {
            int idx = tid + 256 * i;
            int n = idx >> 3, ch = idx & 7;
            size_t src = (size_t)(colBase + n) * K + k0 + ch * 8;
            uint4 vh = *(const uint4*)(Bgh + src);
            uint4 vl = *(const uint4*)(Bgl + src);
            uint32_t so = sw128((uint32_t)(n * 128 + ch * 16));
            *(uint4*)(smem + OBH + so) = vh;
            *(uint4*)(smem + OBL + so) = vl;
        }
        __syncthreads();

#pragma unroll
        for (int ks = 0; ks < 4; ks++) {
            uint32_t ahi[2][4], alo[2][4];
#pragma unroll
            for (int mt = 0; mt < 2; mt++) {
                int row = wm * 32 + mt * 16 + (quad & 1) * 8 + lr;
                uint32_t kb = ks * 32 + (quad >> 1) * 16;
                uint32_t so = sw128((uint32_t)(row * 128) + kb);
                ldsm4(ahi[mt], sb + OAH + so);
                ldsm4(alo[mt], sb + OAL + so);
            }
            uint32_t bhi[4][2], blo[4][2];
#pragma unroll
            for (int p = 0; p < 2; p++) {
                int n = wn * 32 + p * 16 + (quad >> 1) * 8 + lr;
                uint32_t kb = ks * 32 + (quad & 1) * 16;
                uint32_t so = sw128((uint32_t)(n * 128) + kb);
                uint32_t rh[4], rl[4];
                ldsm4(rh, sb + OBH + so);
                ldsm4(rl, sb + OBL + so);
                bhi[p * 2][0] = rh[0]; bhi[p * 2][1] = rh[1];
                bhi[p * 2 + 1][0] = rh[2]; bhi[p * 2 + 1][1] = rh[3];
                blo[p * 2][0] = rl[0]; blo[p * 2][1] = rl[1];
                blo[p * 2 + 1][0] = rl[2]; blo[p * 2 + 1][1] = rl[3];
            }
#pragma unroll
            for (int mt = 0; mt < 2; mt++)
#pragma unroll
                for (int nt = 0; nt < 4; nt++) {
                    mma_bf16(acc[mt][nt], ahi[mt], bhi[nt]);
                    mma_bf16(acc[mt][nt], ahi[mt], blo[nt]);
                    mma_bf16(acc[mt][nt], alo[mt], bhi[nt]);
                }
        }
        __syncthreads();
    }

#pragma unroll
    for (int mt = 0; mt < 2; mt++) {
        int r0 = rowBase + wm * 32 + mt * 16 + (lane >> 2);
        int r1 = r0 + 8;
#pragma unroll
        for (int nt = 0; nt < 4; nt++) {
            int c = colBase + wn * 32 + nt * 8 + (lane & 3) * 2;
            if (r0 < N_NODES)
                *(float2*)(Cout + (size_t)r0 * NTOT + c) = make_float2(acc[mt][nt][0], acc[mt][nt][1]);
            if (r1 < N_NODES)
                *(float2*)(Cout + (size_t)r1 * NTOT + c) = make_float2(acc[mt][nt][2], acc[mt][nt][3]);
        }
    }
}

// ------------------------- CSR aggregation -------------------------
// agg2: h2 = relu(Anorm @ m2 + b2), output split to bf16 hi/lo
__global__ void k_agg2(const float* __restrict__ m, const float* __restrict__ bias) {
    int i = blockIdx.x * 4 + threadIdx.y;
    if (i >= N_NODES) return;
    int c4 = threadIdx.x;  // 0..63
    const float4* m4 = (const float4*)m;
    float d = g_dis[i];
    float dd = d * d;
    float4 v = m4[(size_t)i * (C2 / 4) + c4];
    float4 acc = make_float4(dd * v.x, dd * v.y, dd * v.z, dd * v.w);
    int e0 = g_off[i], e1 = g_off[i + 1];
    for (int e = e0; e < e1; e++) {
        int2 ed = g_edge[e];
        int r = ed.x;
        float w = __int_as_float(ed.y);
        float4 u = m4[(size_t)r * (C2 / 4) + c4];
        acc.x = fmaf(w, u.x, acc.x);
        acc.y = fmaf(w, u.y, acc.y);
        acc.z = fmaf(w, u.z, acc.z);
        acc.w = fmaf(w, u.w, acc.w);
    }
    float4 b = ((const float4*)bias)[c4];
    float ox = fmaxf(acc.x + b.x, 0.0f);
    float oy = fmaxf(acc.y + b.y, 0.0f);
    float oz = fmaxf(acc.z + b.z, 0.0f);
    float ow = fmaxf(acc.w + b.w, 0.0f);
    uint32_t l01, h01 = split2(ox, oy, l01);
    uint32_t l23, h23 = split2(oz, ow, l23);
    size_t o = (size_t)i * C2 + c4 * 4;
    *(uint2*)(g_h2h + o) = make_uint2(h01, h23);
    *(uint2*)(g_h2l + o) = make_uint2(l01, l23);
}

// agg3 fused with mean-pool: pool[batch[i]] += relu(Anorm@m3+b3)[i] * winv[batch[i]]
// block = (32, 8): 8 nodes, 32 threads x float4 = 128 dims. 50000 % 8 == 0.
__global__ void k_agg3pool(const float* __restrict__ m, const float* __restrict__ bias,
                           const int* __restrict__ batch) {
    __shared__ float4 sval[8][32];
    __shared__ int sgid[8];
    int ty = threadIdx.y;
    int c4 = threadIdx.x;  // 0..31
    int i = blockIdx.x * 8 + ty;
    const float4* m4 = (const float4*)m;
    float d = g_dis[i];
    float dd = d * d;
    float4 v = m4[(size_t)i * (C3 / 4) + c4];
    float4 acc = make_float4(dd * v.x, dd * v.y, dd * v.z, dd * v.w);
    int e0 = g_off[i], e1 = g_off[i + 1];
    for (int e = e0; e < e1; e++) {
        int2 ed = g_edge[e];
        int r = ed.x;
        float w = __int_as_float(ed.y);
        float4 u = m4[(size_t)r * (C3 / 4) + c4];
        acc.x = fmaf(w, u.x, acc.x);
        acc.y = fmaf(w, u.y, acc.y);
        acc.z = fmaf(w, u.z, acc.z);
        acc.w = fmaf(w, u.w, acc.w);
    }
    float4 b = ((const float4*)bias)[c4];
    int g = batch[i];
    float wi = g_winv[g];
    float4 o;
    o.x = fmaxf(acc.x + b.x, 0.0f) * wi;
    o.y = fmaxf(acc.y + b.y, 0.0f) * wi;
    o.z = fmaxf(acc.z + b.z, 0.0f) * wi;
    o.w = fmaxf(acc.w + b.w, 0.0f) * wi;
    sval[ty][c4] = o;
    if (c4 == 0) sgid[ty] = g;
    __syncthreads();
    if (ty == 0) {
        // segment-reduce the 8 nodes by graph id (sorted), one atomic set per segment
        float4 run = make_float4(0.f, 0.f, 0.f, 0.f);
        int curg = sgid[0];
#pragma unroll
        for (int k = 0; k < 8; k++) {
            int gg = sgid[k];
            if (gg != curg) {
                float* p = g_pool + curg * C3 + c4 * 4;
                atomicAdd(p + 0, run.x);
                atomicAdd(p + 1, run.y);
                atomicAdd(p + 2, run.z);
                atomicAdd(p + 3, run.w);
                run = make_float4(0.f, 0.f, 0.f, 0.f);
                curg = gg;
            }
            float4 s = sval[k][c4];
            run.x += s.x; run.y += s.y; run.z += s.z; run.w += s.w;
        }
        float* p = g_pool + curg * C3 + c4 * 4;
        atomicAdd(p + 0, run.x);
        atomicAdd(p + 1, run.y);
        atomicAdd(p + 2, run.z);
        atomicAdd(p + 3, run.w);
    }
}

// ------------------------- classifier + next-replay counter reset -------------------------
// grid = 98 x 512 threads: block 0 computes the classifier; ALL blocks zero
// g_cnt/g_state for the NEXT graph replay (module-load init covers run 1).
__global__ void k_cls(const float* __restrict__ Wc, const float* __restrict__ bc,
                      float* __restrict__ out) {
    int tid = threadIdx.x;
    int idx = blockIdx.x * 512 + tid;
    if (idx < N_NODES) g_cnt[idx] = 0;
    if (idx < SCAN_BLOCKS) g_state[idx] = 0u;
    if (blockIdx.x == 0 && tid < NGRAPH) {
        int g = tid;
        float l0 = bc[0], l1 = bc[1];
        for (int c = 0; c < C3; c++) {
            float p = g_pool[g * C3 + c];
            l0 = fmaf(p, Wc[c * 2 + 0], l0);
            l1 = fmaf(p, Wc[c * 2 + 1], l1);
        }
        float mx = fmaxf(l0, l1);
        float lse = mx + logf(expf(l0 - mx) + expf(l1 - mx));
        out[g * 2 + 0] = l0 - lse;
        out[g * 2 + 1] = l1 - lse;
    }
}

// ------------------------- launch -------------------------
extern "C" void kernel_launch(void* const* d_in, const int* in_sizes, int n_in,
                              void* d_out, int out_size) {
    const float* x  = (const float*)d_in[0];
    const float* W1 = (const float*)d_in[1];
    const float* b1 = (const float*)d_in[2];
    const float* W2 = (const float*)d_in[3];
    const float* b2 = (const float*)d_in[4];
    const float* W3 = (const float*)d_in[5];
    const float* b3 = (const float*)d_in[6];
    const float* Wc = (const float*)d_in[7];
    const float* bc = (const float*)d_in[8];
    // JAX default config: x64 disabled -> "int64" arrays are int32.
    const int* ei    = (const int*)d_in[9];
    const int* batch = (const int*)d_in[10];
    float* out = (float*)d_out;

    float *g_aggx_p, *g_m2_p, *g_m3_p;
    __nv_bfloat16 *w2h_p, *w2l_p, *w3h_p, *w3l_p, *h2h_p, *h2l_p;
    cudaGetSymbolAddress((void**)&g_aggx_p, g_aggx);
    cudaGetSymbolAddress((void**)&g_m2_p, g_m2);
    cudaGetSymbolAddress((void**)&g_m3_p, g_m3);
    cudaGetSymbolAddress((void**)&w2h_p, g_Wt2h);
    cudaGetSymbolAddress((void**)&w2l_p, g_Wt2l);
    cudaGetSymbolAddress((void**)&w3h_p, g_Wt3h);
    cudaGetSymbolAddress((void**)&w3l_p, g_Wt3l);
    cudaGetSymbolAddress((void**)&h2h_p, g_h2h);
    cudaGetSymbolAddress((void**)&h2l_p, g_h2l);

    static bool init_done = false;
    static cudaStream_t s2;
    static cudaEvent_t ev1, ev2;
    if (!init_done) {
        cudaFuncSetAttribute((const void*)k_gemm_mma<C1, C2, true>,
                             cudaFuncAttributeMaxDynamicSharedMemorySize, SMEM_G2);
        cudaFuncSetAttribute((const void*)k_gemm_mma<C2, C3, false>,
                             cudaFuncAttributeMaxDynamicSharedMemorySize, SMEM_G3);
        cudaStreamCreateWithFlags(&s2, cudaStreamNonBlocking);
        cudaEventCreateWithFlags(&ev1, cudaEventDisableTiming);
        cudaEventCreateWithFlags(&ev2, cudaEventDisableTiming);
        init_done = true;
    }

    // fork: prep runs on s2 concurrent with CSR build
    cudaEventRecord(ev1, 0);
    cudaStreamWaitEvent(s2, ev1, 0);
    k_prep<<<(C1 * C2 + C2 * C3 + 255) / 256, 256, 0, s2>>>(W2, W3, batch);
    cudaEventRecord(ev2, s2);

    // CSR build (main stream). g_cnt/g_state pre-zeroed (module init / previous k_cls).
    k_count<<<(N_EDGES + 255) / 256, 256>>>(ei);
    k_scan<<<SCAN_BLOCKS, SCAN_TILE>>>();        // single-pass lookback + dis + cur=start
    k_fill<<<(N_EDGES + 255) / 256, 256>>>(ei);
    k_aggx<<<(N_NODES + 255) / 256, 256>>>(x);

    // join: GEMM2 needs prepped weights (and agg3pool needs g_winv/g_pool)
    cudaStreamWaitEvent(0, ev2, 0);

    // fused layer1 + GEMM2 on HMMA tensor cores: m2 = relu(aggx@W1+b1) @ W2
    k_gemm_mma<C1, C2, true><<<dim3(C2 / 64, NBLK), 256, SMEM_G2>>>(
        g_aggx_p, W1, b1, nullptr, nullptr, w2h_p, w2l_p, g_m2_p);
    k_agg2<<<(N_NODES + 3) / 4, dim3(C2 / 4, 4)>>>(g_m2_p, b2);

    // GEMM3: m3 = h2 @ W3
    k_gemm_mma<C2, C3, false><<<dim3(C3 / 64, NBLK), 256, SMEM_G3>>>(
        nullptr, nullptr, nullptr, h2h_p, h2l_p, w3h_p, w3l_p, g_m3_p);

    // agg3 fused with mean pool (atomic segmented reduction)
    k_agg3pool<<<N_NODES / 8, dim3(C3 / 4, 8)>>>(g_m3_p, b3, batch);

    // classifier + zero counters for next replay
    k_cls<<<98, 512>>>(Wc, bc, out);
}

// round 14
// speedup vs baseline: 1.0673x; 1.0021x over previous
#include <cuda_runtime.h>
#include <cuda_bf16.h>
#include <math.h>
#include <stdint.h>

#define N_NODES 50000
#define N_EDGES 800000
#define C1 512
#define C2 256
#define C3 128
#define NGRAPH 100
#define NBLK ((N_NODES + 127) / 128)   // 391
#define NPAD (NBLK * 128)              // 50048

#define SCAN_TILE 256
#define SCAN_BLOCKS ((N_NODES + SCAN_TILE - 1) / SCAN_TILE)  // 196

// ------------------------- helpers -------------------------
__device__ __forceinline__ uint32_t smem_u32(const void* p) {
    uint32_t a;
    asm("{ .reg .u64 t; cvta.to.shared.u64 t, %1; cvt.u32.u64 %0, t; }" : "=r"(a) : "l"(p));
    return a;
}
__device__ __forceinline__ uint32_t sw128(uint32_t o) { return o ^ ((o >> 3) & 0x70); }

__device__ __forceinline__ uint32_t split2(float v0, float v1, uint32_t& lo_out) {
    __nv_bfloat16 h0 = __float2bfloat16(v0);
    __nv_bfloat16 h1 = __float2bfloat16(v1);
    __nv_bfloat16 l0 = __float2bfloat16(v0 - __bfloat162float(h0));
    __nv_bfloat16 l1 = __float2bfloat16(v1 - __bfloat162float(h1));
    __nv_bfloat162 hp = __halves2bfloat162(h0, h1);
    __nv_bfloat162 lp = __halves2bfloat162(l0, l1);
    lo_out = *reinterpret_cast<uint32_t*>(&lp);
    return *reinterpret_cast<uint32_t*>(&hp);
}

__device__ __forceinline__ void ldsm4(uint32_t* r, uint32_t addr) {
    asm volatile("ldmatrix.sync.aligned.m8n8.x4.shared.b16 {%0,%1,%2,%3}, [%4];"
                 : "=r"(r[0]), "=r"(r[1]), "=r"(r[2]), "=r"(r[3]) : "r"(addr));
}

__device__ __forceinline__ void mma_bf16(float* c, const uint32_t* a, const uint32_t* b) {
    asm volatile(
        "mma.sync.aligned.m16n8k16.row.col.f32.bf16.bf16.f32 "
        "{%0,%1,%2,%3}, {%4,%5,%6,%7}, {%8,%9}, {%0,%1,%2,%3};"
        : "+f"(c[0]), "+f"(c[1]), "+f"(c[2]), "+f"(c[3])
        : "r"(a[0]), "r"(a[1]), "r"(a[2]), "r"(a[3]), "r"(b[0]), "r"(b[1]));
}

// ------------------------- scratch (device globals) -------------------------
// NOTE: g_cnt/g_state are zeroed by module-load init on run 1, then re-zeroed
// by k_cls at the END of each run for the next graph replay.
__device__ int   g_cnt[N_NODES];
__device__ int   g_cur[N_NODES];     // pre-biased to segment start by k_scan
__device__ int   g_off[N_NODES + 1];
__device__ unsigned int g_state[SCAN_BLOCKS];   // lookback state: bit30 agg, bit31 prefix
__device__ float g_dis[N_NODES];
__device__ int   g_erow[N_EDGES];    // row index only; w rebuilt from g_dis in consumers

__device__ __align__(16) float g_aggx[N_NODES * 3];
__device__ __align__(16) float g_m2[(size_t)N_NODES * C2];
__device__ __align__(16) float g_m3[(size_t)N_NODES * C3];
__device__ __align__(16) float g_pool[NGRAPH * C3];
__device__ float g_winv[NGRAPH];

// bf16 split weights (transposed to [N][K]) and h2 splits
__device__ __align__(16) __nv_bfloat16 g_Wt2h[C2 * C1];
__device__ __align__(16) __nv_bfloat16 g_Wt2l[C2 * C1];
__device__ __align__(16) __nv_bfloat16 g_Wt3h[C3 * C2];
__device__ __align__(16) __nv_bfloat16 g_Wt3l[C3 * C2];
__device__ __align__(16) __nv_bfloat16 g_h2h[(size_t)NPAD * C2];  // pad rows stay zero
__device__ __align__(16) __nv_bfloat16 g_h2l[(size_t)NPAD * C2];

// ------------------------- CSR build -------------------------
__global__ void k_count(const int* __restrict__ ei) {
    int e = blockIdx.x * blockDim.x + threadIdx.x;
    if (e < N_EDGES) atomicAdd(&g_cnt[ei[N_EDGES + e]], 1);
}

// single-pass scan with decoupled lookback (+ dis + g_cur = segment-start)
__global__ void k_scan() {
    __shared__ int sm[SCAN_TILE];
    __shared__ int sprefix;
    int tid = threadIdx.x;
    int b = blockIdx.x;
    int i = b * SCAN_TILE + tid;
    int v = 0;
    if (i < N_NODES) {
        v = g_cnt[i];
        g_dis[i] = rsqrtf((float)(v + 1));  // +1 self-loop
    }
    sm[tid] = v;
    __syncthreads();
#pragma unroll
    for (int ofs = 1; ofs < SCAN_TILE; ofs <<= 1) {
        int t = (tid >= ofs) ? sm[tid - ofs] : 0;
        __syncthreads();
        sm[tid] += t;
        __syncthreads();
    }
    if (tid == 0) {
        unsigned int total = (unsigned int)sm[SCAN_TILE - 1];
        atomicExch(&g_state[b], (1u << 30) | total);  // aggregate ready
        unsigned int ex = 0;
        for (int j = b - 1; j >= 0; j--) {
            unsigned int s;
            do { s = atomicAdd(&g_state[j], 0u); } while (s == 0u);
            ex += s & 0x3FFFFFFFu;
            if (s & (1u << 31)) break;  // inclusive prefix available
        }
        atomicExch(&g_state[b], (1u << 31) | (ex + total));  // prefix ready
        sprefix = (int)ex;
    }
    __syncthreads();
    if (i < N_NODES) {
        int incl = sprefix + sm[tid];
        g_off[i + 1] = incl;
        g_cur[i] = incl - v;  // segment start: k_fill's atomicAdd returns absolute pos
    }
    if (b == 0 && tid == 0) g_off[0] = 0;
}

// minimal fill: 2 coalesced loads + 1 scattered atomic + 1 scattered 4B store
__global__ void k_fill(const int* __restrict__ ei) {
    int e = blockIdx.x * blockDim.x + threadIdx.x;
    if (e < N_EDGES) {
        int row = ei[e];
        int col = ei[N_EDGES + e];
        int pos = atomicAdd(&g_cur[col], 1);   // absolute position (pre-biased)
        g_erow[pos] = row;
    }
}

// ------------------------- side-stream prep: weight split + graph counts + pool zero -----
__global__ void k_prep(const float* __restrict__ W2, const float* __restrict__ W3,
                       const int* __restrict__ batch) {
    int idx = blockIdx.x * 256 + threadIdx.x;
    if (idx < C1 * C2) {
        int n = idx / C1, k = idx % C1;
        float v = W2[(size_t)k * C2 + n];
        __nv_bfloat16 h = __float2bfloat16(v);
        g_Wt2h[idx] = h;
        g_Wt2l[idx] = __float2bfloat16(v - __bfloat162float(h));
    }
    int idx3 = idx - C1 * C2;
    if (idx3 >= 0 && idx3 < C2 * C3) {
        int n = idx3 / C2, k = idx3 % C2;
        float v = W3[(size_t)k * C3 + n];
        __nv_bfloat16 h = __float2bfloat16(v);
        g_Wt3h[idx3] = h;
        g_Wt3l[idx3] = __float2bfloat16(v - __bfloat162float(h));
    }
    if (idx < NGRAPH * C3) g_pool[idx] = 0.0f;
    if (idx < NGRAPH) {
        // count nodes with batch == idx (batch sorted)
        int lo = 0, hi = N_NODES;
        while (lo < hi) { int m = (lo + hi) >> 1; if (batch[m] < idx) lo = m + 1; else hi = m; }
        int s = lo;
        lo = 0; hi = N_NODES;
        while (lo < hi) { int m = (lo + hi) >> 1; if (batch[m] < idx + 1) lo = m + 1; else hi = m; }
        int cnt = lo - s;
        g_winv[idx] = 1.0f / (float)(cnt > 0 ? cnt : 1);
    }
}

// ------------------------- layer 1 aggregate (3 dims) -------------------------
__global__ void k_aggx(const float* __restrict__ x) {
    int i = blockIdx.x * blockDim.x + threadIdx.x;
    if (i >= N_NODES) return;
    float di = g_dis[i];
    float dd = di * di;
    float a0 = dd * x[i * 3 + 0];
    float a1 = dd * x[i * 3 + 1];
    float a2 = dd * x[i * 3 + 2];
    int e0 = g_off[i], e1 = g_off[i + 1];
    for (int e = e0; e < e1; e++) {
        int r = g_erow[e];
        float w = g_dis[r] * di;
        a0 += w * x[r * 3 + 0];
        a1 += w * x[r * 3 + 1];
        a2 += w * x[r * 3 + 2];
    }
    g_aggx[i * 3 + 0] = a0;
    g_aggx[i * 3 + 1] = a1;
    g_aggx[i * 3 + 2] = a2;
}

// ===================== HMMA split-bf16 GEMM (single-buffered — R7 form) =====================
// Inter-CTA overlap (2 CTAs/SM) hides the fill phase; intra-CTA double-buffering
// measured WORSE (R8: +20us) — do not reintroduce.

#define G2_B1  0
#define G2_W1  2048
#define G2_AX  8192
#define G2_AHI 10240
#define G2_ALO 26624
#define G2_BHI 43008
#define G2_BLO 51200
#define SMEM_G2 59392
#define G3_AHI 0
#define G3_ALO 16384
#define G3_BHI 32768
#define G3_BLO 40960
#define SMEM_G3 49152

template <int K, int NTOT, bool GENA>
__global__ __launch_bounds__(256) void k_gemm_mma(
    const float* __restrict__ aggx, const float* __restrict__ W1,
    const float* __restrict__ b1,
    const __nv_bfloat16* __restrict__ Agh, const __nv_bfloat16* __restrict__ Agl,
    const __nv_bfloat16* __restrict__ Bgh, const __nv_bfloat16* __restrict__ Bgl,
    float* __restrict__ Cout) {
    extern __shared__ char smem[];
    const uint32_t sb = smem_u32(smem);
    const int tid = threadIdx.x;
    const int lane = tid & 31;
    const int wid = tid >> 5;
    const int wm = wid >> 1;
    const int wn = wid & 1;
    const int rowBase = blockIdx.y * 128;
    const int colBase = blockIdx.x * 64;

    constexpr int OAH = GENA ? G2_AHI : G3_AHI;
    constexpr int OAL = GENA ? G2_ALO : G3_ALO;
    constexpr int OBH = GENA ? G2_BHI : G3_BHI;
    constexpr int OBL = GENA ? G2_BLO : G3_BLO;

    float* b1s = (float*)(smem + G2_B1);
    float* W1s = (float*)(smem + G2_W1);
    float(*ax)[4] = (float(*)[4])(smem + G2_AX);

    if constexpr (GENA) {
        for (int i = tid; i < C1; i += 256) b1s[i] = b1[i];
        for (int i = tid; i < 3 * C1; i += 256) W1s[i] = W1[i];
        for (int i = tid; i < 128 * 3; i += 256) {
            int r = i / 3, j = i % 3;
            int gr = rowBase + r;
            ax[r][j] = (gr < N_NODES) ? aggx[gr * 3 + j] : 0.0f;
        }
        __syncthreads();
    }

    float acc[2][4][4];
#pragma unroll
    for (int mt = 0; mt < 2; mt++)
#pragma unroll
        for (int nt = 0; nt < 4; nt++)
#pragma unroll
            for (int j = 0; j < 4; j++) acc[mt][nt][j] = 0.0f;

    const int quad = lane >> 3;
    const int lr = lane & 7;

    for (int k0 = 0; k0 < K; k0 += 64) {
        if constexpr (GENA) {
            const int kp = tid & 31;
            const int rg = tid >> 5;
            const int k = k0 + kp * 2;
            const float w0a = W1s[k], w0b = W1s[k + 1];
            const float w1a = W1s[C1 + k], w1b = W1s[C1 + k + 1];
            const float w2a = W1s[2 * C1 + k], w2b = W1s[2 * C1 + k + 1];
            const float ba = b1s[k], bb = b1s[k + 1];
#pragma unroll 4
            for (int rr = 0; rr < 16; rr++) {
                int r = rg * 16 + rr;
                float a0 = ax[r][0], a1 = ax[r][1], a2 = ax[r][2];
                float v0 = fmaxf(ba + a0 * w0a + a1 * w1a + a2 * w2a, 0.0f);
                float v1 = fmaxf(bb + a0 * w0b + a1 * w1b + a2 * w2b, 0.0f);
                if (rowBase + r >= N_NODES) { v0 = 0.0f; v1 = 0.0f; }
                uint32_t lw, hw = split2(v0, v1, lw);
                uint32_t so = sw128((uint32_t)(r * 128 + kp * 4));
                *(uint32_t*)(smem + OAH + so) = hw;
                *(uint32_t*)(smem + OAL + so) = lw;
            }
        } else {
#pragma unroll
            for (int i = 0; i < 4; i++) {
                int idx = tid + 256 * i;
                int r = idx >> 3, ch = idx & 7;
                size_t src = (size_t)(rowBase + r) * K + k0 + ch * 8;
                uint4 vh = *(const uint4*)(Agh + src);
                uint4 vl = *(const uint4*)(Agl + src);
                uint32_t so = sw128((uint32_t)(r * 128 + ch * 16));
                *(uint4*)(smem + OAH + so) = vh;
                *(uint4*)(smem + OAL + so) = vl;
            }
        }
#pragma unroll
        for (int i = 0; i < 2; i++) {
            int idx = tid + 256 * i;
            int n = idx >> 3, ch = idx & 7;
            size_t src = (size_t)(colBase + n) * K + k0 + ch * 8;
            uint4 vh = *(const uint4*)(Bgh + src);
            uint4 vl = *(const uint4*)(Bgl + src);
            uint32_t so = sw128((uint32_t)(n * 128 + ch * 16));
            *(uint4*)(smem + OBH + so) = vh;
            *(uint4*)(smem + OBL + so) = vl;
        }
        __syncthreads();

#pragma unroll
        for (int ks = 0; ks < 4; ks++) {
            uint32_t ahi[2][4], alo[2][4];
#pragma unroll
            for (int mt = 0; mt < 2; mt++) {
                int row = wm * 32 + mt * 16 + (quad & 1) * 8 + lr;
                uint32_t kb = ks * 32 + (quad >> 1) * 16;
                uint32_t so = sw128((uint32_t)(row * 128) + kb);
                ldsm4(ahi[mt], sb + OAH + so);
                ldsm4(alo[mt], sb + OAL + so);
            }
            uint32_t bhi[4][2], blo[4][2];
#pragma unroll
            for (int p = 0; p < 2; p++) {
                int n = wn * 32 + p * 16 + (quad >> 1) * 8 + lr;
                uint32_t kb = ks * 32 + (quad & 1) * 16;
                uint32_t so = sw128((uint32_t)(n * 128) + kb);
                uint32_t rh[4], rl[4];
                ldsm4(rh, sb + OBH + so);
                ldsm4(rl, sb + OBL + so);
                bhi[p * 2][0] = rh[0]; bhi[p * 2][1] = rh[1];
                bhi[p * 2 + 1][0] = rh[2]; bhi[p * 2 + 1][1] = rh[3];
                blo[p * 2][0] = rl[0]; blo[p * 2][1] = rl[1];
                blo[p * 2 + 1][0] = rl[2]; blo[p * 2 + 1][1] = rl[3];
            }
#pragma unroll
            for (int mt = 0; mt < 2; mt++)
#pragma unroll
                for (int nt = 0; nt < 4; nt++) {
                    mma_bf16(acc[mt][nt], ahi[mt], bhi[nt]);
                    mma_bf16(acc[mt][nt], ahi[mt], blo[nt]);
                    mma_bf16(acc[mt][nt], alo[mt], bhi[nt]);
                }
        }
        __syncthreads();
    }

#pragma unroll
    for (int mt = 0; mt < 2; mt++) {
        int r0 = rowBase + wm * 32 + mt * 16 + (lane >> 2);
        int r1 = r0 + 8;
#pragma unroll
        for (int nt = 0; nt < 4; nt++) {
            int c = colBase + wn * 32 + nt * 8 + (lane & 3) * 2;
            if (r0 < N_NODES)
                *(float2*)(Cout + (size_t)r0 * NTOT + c) = make_float2(acc[mt][nt][0], acc[mt][nt][1]);
            if (r1 < N_NODES)
                *(float2*)(Cout + (size_t)r1 * NTOT + c) = make_float2(acc[mt][nt][2], acc[mt][nt][3]);
        }
    }
}

// ------------------------- CSR aggregation -------------------------
// agg2: h2 = relu(Anorm @ m2 + b2), output split to bf16 hi/lo
__global__ void k_agg2(const float* __restrict__ m, const float* __restrict__ bias) {
    int i = blockIdx.x * 4 + threadIdx.y;
    if (i >= N_NODES) return;
    int c4 = threadIdx.x;  // 0..63
    const float4* m4 = (const float4*)m;
    float di = g_dis[i];
    float dd = di * di;
    float4 v = m4[(size_t)i * (C2 / 4) + c4];
    float4 acc = make_float4(dd * v.x, dd * v.y, dd * v.z, dd * v.w);
    int e0 = g_off[i], e1 = g_off[i + 1];
    for (int e = e0; e < e1; e++) {
        int r = g_erow[e];
        float w = g_dis[r] * di;
        float4 u = m4[(size_t)r * (C2 / 4) + c4];
        acc.x = fmaf(w, u.x, acc.x);
        acc.y = fmaf(w, u.y, acc.y);
        acc.z = fmaf(w, u.z, acc.z);
        acc.w = fmaf(w, u.w, acc.w);
    }
    float4 b = ((const float4*)bias)[c4];
    float ox = fmaxf(acc.x + b.x, 0.0f);
    float oy = fmaxf(acc.y + b.y, 0.0f);
    float oz = fmaxf(acc.z + b.z, 0.0f);
    float ow = fmaxf(acc.w + b.w, 0.0f);
    uint32_t l01, h01 = split2(ox, oy, l01);
    uint32_t l23, h23 = split2(oz, ow, l23);
    size_t o = (size_t)i * C2 + c4 * 4;
    *(uint2*)(g_h2h + o) = make_uint2(h01, h23);
    *(uint2*)(g_h2l + o) = make_uint2(l01, l23);
}

// agg3 fused with mean-pool: pool[batch[i]] += relu(Anorm@m3+b3)[i] * winv[batch[i]]
// block = (32, 8): 8 nodes, 32 threads x float4 = 128 dims. 50000 % 8 == 0.
__global__ void k_agg3pool(const float* __restrict__ m, const float* __restrict__ bias,
                           const int* __restrict__ batch) {
    __shared__ float4 sval[8][32];
    __shared__ int sgid[8];
    int ty = threadIdx.y;
    int c4 = threadIdx.x;  // 0..31
    int i = blockIdx.x * 8 + ty;
    const float4* m4 = (const float4*)m;
    float di = g_dis[i];
    float dd = di * di;
    float4 v = m4[(size_t)i * (C3 / 4) + c4];
    float4 acc = make_float4(dd * v.x, dd * v.y, dd * v.z, dd * v.w);
    int e0 = g_off[i], e1 = g_off[i + 1];
    for (int e = e0; e < e1; e++) {
        int r = g_erow[e];
        float w = g_dis[r] * di;
        float4 u = m4[(size_t)r * (C3 / 4) + c4];
        acc.x = fmaf(w, u.x, acc.x);
        acc.y = fmaf(w, u.y, acc.y);
        acc.z = fmaf(w, u.z, acc.z);
        acc.w = fmaf(w, u.w, acc.w);
    }
    float4 b = ((const float4*)bias)[c4];
    int g = batch[i];
    float wi = g_winv[g];
    float4 o;
    o.x = fmaxf(acc.x + b.x, 0.0f) * wi;
    o.y = fmaxf(acc.y + b.y, 0.0f) * wi;
    o.z = fmaxf(acc.z + b.z, 0.0f) * wi;
    o.w = fmaxf(acc.w + b.w, 0.0f) * wi;
    sval[ty][c4] = o;
    if (c4 == 0) sgid[ty] = g;
    __syncthreads();
    if (ty == 0) {
        // segment-reduce the 8 nodes by graph id (sorted), one atomic set per segment
        float4 run = make_float4(0.f, 0.f, 0.f, 0.f);
        int curg = sgid[0];
#pragma unroll
        for (int k = 0; k < 8; k++) {
            int gg = sgid[k];
            if (gg != curg) {
                float* p = g_pool + curg * C3 + c4 * 4;
                atomicAdd(p + 0, run.x);
                atomicAdd(p + 1, run.y);
                atomicAdd(p + 2, run.z);
                atomicAdd(p + 3, run.w);
                run = make_float4(0.f, 0.f, 0.f, 0.f);
                curg = gg;
            }
            float4 s = sval[k][c4];
            run.x += s.x; run.y += s.y; run.z += s.z; run.w += s.w;
        }
        float* p = g_pool + curg * C3 + c4 * 4;
        atomicAdd(p + 0, run.x);
        atomicAdd(p + 1, run.y);
        atomicAdd(p + 2, run.z);
        atomicAdd(p + 3, run.w);
    }
}

// ------------------------- classifier + next-replay counter reset -------------------------
// grid = 98 x 512 threads: block 0 computes the classifier; ALL blocks zero
// g_cnt/g_state for the NEXT graph replay (module-load init covers run 1).
__global__ void k_cls(const float* __restrict__ Wc, const float* __restrict__ bc,
                      float* __restrict__ out) {
    int tid = threadIdx.x;
    int idx = blockIdx.x * 512 + tid;
    if (idx < N_NODES) g_cnt[idx] = 0;
    if (idx < SCAN_BLOCKS) g_state[idx] = 0u;
    if (blockIdx.x == 0 && tid < NGRAPH) {
        int g = tid;
        float l0 = bc[0], l1 = bc[1];
        for (int c = 0; c < C3; c++) {
            float p = g_pool[g * C3 + c];
            l0 = fmaf(p, Wc[c * 2 + 0], l0);
            l1 = fmaf(p, Wc[c * 2 + 1], l1);
        }
        float mx = fmaxf(l0, l1);
        float lse = mx + logf(expf(l0 - mx) + expf(l1 - mx));
        out[g * 2 + 0] = l0 - lse;
        out[g * 2 + 1] = l1 - lse;
    }
}

// ------------------------- launch -------------------------
extern "C" void kernel_launch(void* const* d_in, const int* in_sizes, int n_in,
                              void* d_out, int out_size) {
    const float* x  = (const float*)d_in[0];
    const float* W1 = (const float*)d_in[1];
    const float* b1 = (const float*)d_in[2];
    const float* W2 = (const float*)d_in[3];
    const float* b2 = (const float*)d_in[4];
    const float* W3 = (const float*)d_in[5];
    const float* b3 = (const float*)d_in[6];
    const float* Wc = (const float*)d_in[7];
    const float* bc = (const float*)d_in[8];
    // JAX default config: x64 disabled -> "int64" arrays are int32.
    const int* ei    = (const int*)d_in[9];
    const int* batch = (const int*)d_in[10];
    float* out = (float*)d_out;

    float *g_aggx_p, *g_m2_p, *g_m3_p;
    __nv_bfloat16 *w2h_p, *w2l_p, *w3h_p, *w3l_p, *h2h_p, *h2l_p;
    cudaGetSymbolAddress((void**)&g_aggx_p, g_aggx);
    cudaGetSymbolAddress((void**)&g_m2_p, g_m2);
    cudaGetSymbolAddress((void**)&g_m3_p, g_m3);
    cudaGetSymbolAddress((void**)&w2h_p, g_Wt2h);
    cudaGetSymbolAddress((void**)&w2l_p, g_Wt2l);
    cudaGetSymbolAddress((void**)&w3h_p, g_Wt3h);
    cudaGetSymbolAddress((void**)&w3l_p, g_Wt3l);
    cudaGetSymbolAddress((void**)&h2h_p, g_h2h);
    cudaGetSymbolAddress((void**)&h2l_p, g_h2l);

    static bool init_done = false;
    static cudaStream_t s2;
    static cudaEvent_t ev1, ev2;
    if (!init_done) {
        cudaFuncSetAttribute((const void*)k_gemm_mma<C1, C2, true>,
                             cudaFuncAttributeMaxDynamicSharedMemorySize, SMEM_G2);
        cudaFuncSetAttribute((const void*)k_gemm_mma<C2, C3, false>,
                             cudaFuncAttributeMaxDynamicSharedMemorySize, SMEM_G3);
        cudaStreamCreateWithFlags(&s2, cudaStreamNonBlocking);
        cudaEventCreateWithFlags(&ev1, cudaEventDisableTiming);
        cudaEventCreateWithFlags(&ev2, cudaEventDisableTiming);
        init_done = true;
    }

    // fork: prep runs on s2 concurrent with CSR build
    cudaEventRecord(ev1, 0);
    cudaStreamWaitEvent(s2, ev1, 0);
    k_prep<<<(C1 * C2 + C2 * C3 + 255) / 256, 256, 0, s2>>>(W2, W3, batch);
    cudaEventRecord(ev2, s2);

    // CSR build (main stream). g_cnt/g_state pre-zeroed (module init / previous k_cls).
    k_count<<<(N_EDGES + 255) / 256, 256>>>(ei);
    k_scan<<<SCAN_BLOCKS, SCAN_TILE>>>();        // single-pass lookback + dis + cur=start
    k_fill<<<(N_EDGES + 255) / 256, 256>>>(ei);
    k_aggx<<<(N_NODES + 255) / 256, 256>>>(x);

    // join: GEMM2 needs prepped weights (and agg3pool needs g_winv/g_pool)
    cudaStreamWaitEvent(0, ev2, 0);

    // fused layer1 + GEMM2 on HMMA tensor cores: m2 = relu(aggx@W1+b1) @ W2
    k_gemm_mma<C1, C2, true><<<dim3(C2 / 64, NBLK), 256, SMEM_G2>>>(
        g_aggx_p, W1, b1, nullptr, nullptr, w2h_p, w2l_p, g_m2_p);
    k_agg2<<<(N_NODES + 3) / 4, dim3(C2 / 4, 4)>>>(g_m2_p, b2);

    // GEMM3: m3 = h2 @ W3
    k_gemm_mma<C2, C3, false><<<dim3(C3 / 64, NBLK), 256, SMEM_G3>>>(
        nullptr, nullptr, nullptr, h2h_p, h2l_p, w3h_p, w3l_p, g_m3_p);

    // agg3 fused with mean pool (atomic segmented reduction)
    k_agg3pool<<<N_NODES / 8, dim3(C3 / 4, 8)>>>(g_m3_p, b3, batch);

    // classifier + zero counters for next replay
    k_cls<<<98, 512>>>(Wc, bc, out);
}